// round 1
// baseline (speedup 1.0000x reference)
#include <cuda_runtime.h>
#include <math.h>

// ---------------- problem constants ----------------
#define BB   2
#define SQ   1024
#define SKV  4096
#define DQ_  1024
#define DKV_ 768
#define NH   16
#define HD   64

// ---------------- scratch (static device globals; no allocs) ----------------
__device__ float g_Q[BB * SQ * DQ_];     // (B*Sq, 1024) == per-head contiguous (1024,64) blocks
__device__ float g_K[BB * SKV * DQ_];    // (B*Skv, 1024) == per-head contiguous (4096,64) blocks
__device__ float g_V[BB * SKV * DQ_];
__device__ float g_AO[BB * SQ * DQ_];    // attention output, (B, Sq, DQ) layout

// =====================================================================
// NT GEMM: C[M,N] = sum_k A[M,K] * B[N,K]   (both operands K-contiguous)
// 128x128 tile, BK=16, 256 threads, 8x8 microtile (split 4+4 rows/cols)
// =====================================================================
__global__ __launch_bounds__(256) void gemm_nt_kernel(
    const float* __restrict__ A, const float* __restrict__ Bm,
    float* __restrict__ C, int M, int N, int K_)
{
    __shared__ float As[16][128];   // [k][m] transposed
    __shared__ float Bs[16][128];   // [k][n] transposed

    const int tid = threadIdx.x;
    const int tx = tid & 15;        // 0..15 -> N microtile
    const int ty = tid >> 4;        // 0..15 -> M microtile
    const int bm = blockIdx.y * 128;
    const int bn = blockIdx.x * 128;
    const int r  = tid & 63;        // load row within 64-group
    const int c4 = tid >> 6;        // 0..3 -> which float4 of the BK=16 slice

    float acc[8][8] = {};

    const float* Ar0 = A  + (size_t)(bm + r)      * K_ + c4 * 4;
    const float* Ar1 = A  + (size_t)(bm + r + 64) * K_ + c4 * 4;
    const float* Br0 = Bm + (size_t)(bn + r)      * K_ + c4 * 4;
    const float* Br1 = Bm + (size_t)(bn + r + 64) * K_ + c4 * 4;

    for (int k0 = 0; k0 < K_; k0 += 16) {
        float4 a0 = *(const float4*)(Ar0 + k0);
        float4 a1 = *(const float4*)(Ar1 + k0);
        float4 b0 = *(const float4*)(Br0 + k0);
        float4 b1 = *(const float4*)(Br1 + k0);
        __syncthreads();   // previous tile's compute done before overwrite
        As[c4*4+0][r]    = a0.x; As[c4*4+1][r]    = a0.y;
        As[c4*4+2][r]    = a0.z; As[c4*4+3][r]    = a0.w;
        As[c4*4+0][r+64] = a1.x; As[c4*4+1][r+64] = a1.y;
        As[c4*4+2][r+64] = a1.z; As[c4*4+3][r+64] = a1.w;
        Bs[c4*4+0][r]    = b0.x; Bs[c4*4+1][r]    = b0.y;
        Bs[c4*4+2][r]    = b0.z; Bs[c4*4+3][r]    = b0.w;
        Bs[c4*4+0][r+64] = b1.x; Bs[c4*4+1][r+64] = b1.y;
        Bs[c4*4+2][r+64] = b1.z; Bs[c4*4+3][r+64] = b1.w;
        __syncthreads();

        #pragma unroll
        for (int kk = 0; kk < 16; kk++) {
            float av[8], bv[8];
            *(float4*)(av)     = *(const float4*)&As[kk][ty * 4];
            *(float4*)(av + 4) = *(const float4*)&As[kk][64 + ty * 4];
            *(float4*)(bv)     = *(const float4*)&Bs[kk][tx * 4];
            *(float4*)(bv + 4) = *(const float4*)&Bs[kk][64 + tx * 4];
            #pragma unroll
            for (int i = 0; i < 8; i++)
                #pragma unroll
                for (int j = 0; j < 8; j++)
                    acc[i][j] += av[i] * bv[j];
        }
    }

    #pragma unroll
    for (int i = 0; i < 8; i++) {
        int row = bm + ((i < 4) ? (ty * 4 + i) : (64 + ty * 4 + i - 4));
        float* Cp = C + (size_t)row * N + bn;
        *(float4*)(Cp + tx * 4)      = make_float4(acc[i][0], acc[i][1], acc[i][2], acc[i][3]);
        *(float4*)(Cp + 64 + tx * 4) = make_float4(acc[i][4], acc[i][5], acc[i][6], acc[i][7]);
    }
}

// =====================================================================
// Flash attention, fp32. One CTA = (bh, 64-query tile).
// Per head: Q'(1024,64), K'(4096,64), V'(4096,64) all contiguous.
// scores = Q K^T / 64 (scale folded into Q at load), softmax over 4096.
// smem: Qst[d][m] 16KB | Kst[d][n] 16KB (aliased by Ps[m][n]) | Vs[n][68] 17KB
// =====================================================================
#define FLASH_SMEM ((64 * 64 + 64 * 64 + 64 * 68) * 4)

__global__ __launch_bounds__(256) void flash_kernel()
{
    extern __shared__ float smem[];
    float* Qst = smem;              // [64][64]  d-major
    float* KP  = smem + 64 * 64;    // [64][64]  Kst d-major, later Ps m-major
    float* Vs  = smem + 2 * 64 * 64;// [64][68]  n-major, padded pitch

    const int tid = threadIdx.x;
    const int tx  = tid & 15;
    const int ty  = tid >> 4;
    const int r   = tid & 63;
    const int cg  = tid >> 6;       // 0..3
    const int bh  = blockIdx.y;
    const int b   = bh >> 4, h = bh & 15;
    const int q0  = blockIdx.x * 64;

    const float* Qh = g_Q + (size_t)bh * (SQ * HD);
    const float* Kh = g_K + (size_t)bh * (SKV * HD);
    const float* Vh = g_V + (size_t)bh * (SKV * HD);

    // Q tile -> Qst[d][m], pre-scaled by 1/HD
    const float qs = 1.0f / (float)HD;
    #pragma unroll
    for (int it = 0; it < 4; it++) {
        int cc = cg + it * 4;       // float4 column group 0..15
        float4 q = *(const float4*)(Qh + (size_t)(q0 + r) * HD + cc * 4);
        Qst[(cc * 4 + 0) * 64 + r] = q.x * qs;
        Qst[(cc * 4 + 1) * 64 + r] = q.y * qs;
        Qst[(cc * 4 + 2) * 64 + r] = q.z * qs;
        Qst[(cc * 4 + 3) * 64 + r] = q.w * qs;
    }

    float m_i[4], l_i[4], o[4][4];
    #pragma unroll
    for (int i = 0; i < 4; i++) {
        m_i[i] = -INFINITY; l_i[i] = 0.0f;
        #pragma unroll
        for (int j = 0; j < 4; j++) o[i][j] = 0.0f;
    }

    for (int kc = 0; kc < SKV / 64; kc++) {
        const int n0 = kc * 64;
        float4 kv[4], vv[4];
        #pragma unroll
        for (int it = 0; it < 4; it++) {
            int cc = cg + it * 4;
            kv[it] = *(const float4*)(Kh + (size_t)(n0 + r) * HD + cc * 4);
            vv[it] = *(const float4*)(Vh + (size_t)(n0 + r) * HD + cc * 4);
        }
        __syncthreads();            // prior chunk's PV reads of KP/Vs done
        #pragma unroll
        for (int it = 0; it < 4; it++) {
            int cc = cg + it * 4;
            KP[(cc * 4 + 0) * 64 + r] = kv[it].x;
            KP[(cc * 4 + 1) * 64 + r] = kv[it].y;
            KP[(cc * 4 + 2) * 64 + r] = kv[it].z;
            KP[(cc * 4 + 3) * 64 + r] = kv[it].w;
            *(float4*)&Vs[r * 68 + cc * 4] = vv[it];
        }
        __syncthreads();

        // S = (Q/64) K^T, 4x4 per thread
        float s[4][4] = {};
        #pragma unroll 16
        for (int d = 0; d < 64; d++) {
            float4 a = *(const float4*)&Qst[d * 64 + ty * 4];
            float4 bq = *(const float4*)&KP[d * 64 + tx * 4];
            s[0][0] += a.x * bq.x; s[0][1] += a.x * bq.y; s[0][2] += a.x * bq.z; s[0][3] += a.x * bq.w;
            s[1][0] += a.y * bq.x; s[1][1] += a.y * bq.y; s[1][2] += a.y * bq.z; s[1][3] += a.y * bq.w;
            s[2][0] += a.z * bq.x; s[2][1] += a.z * bq.y; s[2][2] += a.z * bq.z; s[2][3] += a.z * bq.w;
            s[3][0] += a.w * bq.x; s[3][1] += a.w * bq.y; s[3][2] += a.w * bq.z; s[3][3] += a.w * bq.w;
        }
        __syncthreads();            // Kst reads done before Ps overwrites it

        // online softmax (row group = 16 tx lanes, shuffle-reduce)
        #pragma unroll
        for (int ri = 0; ri < 4; ri++) {
            float mx = fmaxf(fmaxf(s[ri][0], s[ri][1]), fmaxf(s[ri][2], s[ri][3]));
            #pragma unroll
            for (int off = 1; off < 16; off <<= 1)
                mx = fmaxf(mx, __shfl_xor_sync(0xffffffffu, mx, off));
            float mnew = fmaxf(m_i[ri], mx);
            float corr = __expf(m_i[ri] - mnew);
            float sum = 0.0f;
            #pragma unroll
            for (int j = 0; j < 4; j++) {
                s[ri][j] = __expf(s[ri][j] - mnew);
                sum += s[ri][j];
            }
            #pragma unroll
            for (int off = 1; off < 16; off <<= 1)
                sum += __shfl_xor_sync(0xffffffffu, sum, off);
            l_i[ri] = l_i[ri] * corr + sum;
            m_i[ri] = mnew;
            #pragma unroll
            for (int j = 0; j < 4; j++) o[ri][j] *= corr;
            *(float4*)&KP[(ty * 4 + ri) * 64 + tx * 4] =
                make_float4(s[ri][0], s[ri][1], s[ri][2], s[ri][3]);
        }
        __syncthreads();            // Ps fully written

        // O += P V : thread cols = tx*4..+4 of hd
        #pragma unroll 8
        for (int k = 0; k < 64; k++) {
            float4 v = *(const float4*)&Vs[k * 68 + tx * 4];
            #pragma unroll
            for (int ri = 0; ri < 4; ri++) {
                float p = KP[(ty * 4 + ri) * 64 + k];   // broadcast within row group
                o[ri][0] += p * v.x; o[ri][1] += p * v.y;
                o[ri][2] += p * v.z; o[ri][3] += p * v.w;
            }
        }
    }

    // epilogue: AO[b, s', h*64 + d']
    float* AOp = g_AO + (size_t)b * (SQ * DQ_) + h * HD;
    #pragma unroll
    for (int ri = 0; ri < 4; ri++) {
        float inv = 1.0f / l_i[ri];
        int srow = q0 + ty * 4 + ri;
        *(float4*)&AOp[(size_t)srow * DQ_ + tx * 4] =
            make_float4(o[ri][0] * inv, o[ri][1] * inv, o[ri][2] * inv, o[ri][3] * inv);
    }
}

// =====================================================================
// launch
// =====================================================================
extern "C" void kernel_launch(void* const* d_in, const int* in_sizes, int n_in,
                              void* d_out, int out_size)
{
    (void)in_sizes; (void)n_in; (void)out_size;
    const float* x_q  = (const float*)d_in[0];
    const float* x_kv = (const float*)d_in[1];
    const float* Wq   = (const float*)d_in[2];
    const float* Wk   = (const float*)d_in[3];
    const float* Wv   = (const float*)d_in[4];
    const float* Wo   = (const float*)d_in[5];
    float* out = (float*)d_out;

    float *Q, *K, *V, *AO;
    cudaGetSymbolAddress((void**)&Q,  g_Q);
    cudaGetSymbolAddress((void**)&K,  g_K);
    cudaGetSymbolAddress((void**)&V,  g_V);
    cudaGetSymbolAddress((void**)&AO, g_AO);

    cudaFuncSetAttribute(flash_kernel,
                         cudaFuncAttributeMaxDynamicSharedMemorySize, FLASH_SMEM);

    dim3 blk(256);
    // Q = x_q @ Wq^T          (2048 x 1024 x 1024)
    gemm_nt_kernel<<<dim3(DQ_ / 128, (BB * SQ) / 128), blk>>>(x_q, Wq, Q, BB * SQ, DQ_, DQ_);
    // K = x_kv @ Wk^T         (8192 x 1024 x 768)
    gemm_nt_kernel<<<dim3(DQ_ / 128, (BB * SKV) / 128), blk>>>(x_kv, Wk, K, BB * SKV, DQ_, DKV_);
    // V = x_kv @ Wv^T
    gemm_nt_kernel<<<dim3(DQ_ / 128, (BB * SKV) / 128), blk>>>(x_kv, Wv, V, BB * SKV, DQ_, DKV_);
    // attention (32 heads x 16 query tiles)
    flash_kernel<<<dim3(SQ / 64, BB * NH), blk, FLASH_SMEM>>>();
    // out = AO @ Wo^T
    gemm_nt_kernel<<<dim3(DQ_ / 128, (BB * SQ) / 128), blk>>>(AO, Wo, out, BB * SQ, DQ_, DQ_);
}

// round 5
// speedup vs baseline: 1.3167x; 1.3167x over previous
#include <cuda_runtime.h>
#include <math.h>
#include <cstdint>

// ---------------- problem constants ----------------
#define BB   2
#define SQ   1024
#define SKV  4096
#define DQ_  1024
#define DKV_ 768
#define NH   16
#define HD   64

// ---------------- scratch ----------------
__device__ float g_Q [BB * SQ  * DQ_];
__device__ float g_K [BB * SKV * DQ_];
__device__ float g_V [BB * SKV * DQ_];
__device__ float g_AO[BB * SQ  * DQ_];
// tf32-rounded operand copies (Q/K projection path only)
__device__ float g_xq [BB * SQ  * DQ_];
__device__ float g_xkv[BB * SKV * DKV_];
__device__ float g_wq [DQ_ * DQ_];
__device__ float g_wk [DQ_ * DKV_];

// =====================================================================
// helpers
// =====================================================================
__device__ __forceinline__ uint32_t smem_u32(const void* p) {
    uint32_t a;
    asm("{ .reg .u64 t; cvta.to.shared.u64 t, %1; cvt.u32.u64 %0, t; }" : "=r"(a) : "l"(p));
    return a;
}
__device__ __forceinline__ float rna_tf32(float x) {
    uint32_t r;
    asm("cvt.rna.tf32.f32 %0, %1;" : "=r"(r) : "f"(x));
    return __uint_as_float(r);
}
__device__ __forceinline__ void cp16(uint32_t dst, const void* src) {
    asm volatile("cp.async.cg.shared.global [%0], [%1], 16;" :: "r"(dst), "l"(src) : "memory");
}
__device__ __forceinline__ void cp_commit() {
    asm volatile("cp.async.commit_group;" ::: "memory");
}
__device__ __forceinline__ void cp_wait1() {
    asm volatile("cp.async.wait_group 1;" ::: "memory");
}

// D += A(tf32) * B(tf32), m16n8k8, A row-major, B col-major
__device__ __forceinline__ void mma_tf32(float* d, const float* a, const float* b) {
    asm volatile(
        "mma.sync.aligned.m16n8k8.row.col.f32.tf32.tf32.f32 "
        "{%0,%1,%2,%3}, {%4,%5,%6,%7}, {%8,%9}, {%0,%1,%2,%3};"
        : "+f"(d[0]), "+f"(d[1]), "+f"(d[2]), "+f"(d[3])
        : "r"(__float_as_uint(a[0])), "r"(__float_as_uint(a[1])),
          "r"(__float_as_uint(a[2])), "r"(__float_as_uint(a[3])),
          "r"(__float_as_uint(b[0])), "r"(__float_as_uint(b[1])));
}

// =====================================================================
// tf32 rounding prepass
// =====================================================================
__global__ void round_kernel(const float4* __restrict__ in, float4* __restrict__ out, int n4) {
    int i = blockIdx.x * blockDim.x + threadIdx.x;
    if (i < n4) {
        float4 v = in[i];
        v.x = rna_tf32(v.x); v.y = rna_tf32(v.y);
        v.z = rna_tf32(v.z); v.w = rna_tf32(v.w);
        out[i] = v;
    }
}

// =====================================================================
// tf32 mma.sync NT GEMM: C[M,N] = A[M,K] * B[N,K]^T  (Q/K projections)
// CTA 128x128, BK=32, 3-stage cp.async pipeline, 256 threads (8 warps).
// =====================================================================
#define GP        36
#define STAGE_F   (2 * 128 * GP)
#define GSTAGES   3
#define GEMM_SMEM (GSTAGES * STAGE_F * 4)

__global__ __launch_bounds__(256) void gemm_mma(
    const float* __restrict__ A, const float* __restrict__ B,
    float* __restrict__ C, int M, int N, int K_)
{
    extern __shared__ float sm[];
    const uint32_t sb = smem_u32(sm);

    const int tid  = threadIdx.x;
    const int wid  = tid >> 5;
    const int lane = tid & 31;
    const int r8   = lane >> 2;
    const int c4   = lane & 3;
    const int wm   = (wid & 1) * 64;
    const int wn   = (wid >> 1) * 32;
    const int bm   = blockIdx.y * 128;
    const int bn   = blockIdx.x * 128;
    const int nk   = K_ >> 5;

    float acc[4][4][4];
    #pragma unroll
    for (int mt = 0; mt < 4; mt++)
        #pragma unroll
        for (int nt = 0; nt < 4; nt++)
            #pragma unroll
            for (int j = 0; j < 4; j++) acc[mt][nt][j] = 0.0f;

    auto issue = [&](int kc) {
        const int s = kc % GSTAGES;
        const uint32_t dA = sb + (uint32_t)(s * STAGE_F) * 4;
        const uint32_t dB = dA + 128 * GP * 4;
        const float* gA = A + (size_t)bm * K_ + kc * 32;
        const float* gB = B + (size_t)bn * K_ + kc * 32;
        #pragma unroll
        for (int i = 0; i < 4; i++) {
            const int idx = tid + 256 * i;
            const int row = idx >> 3, cg = idx & 7;
            cp16(dA + (row * GP + cg * 4) * 4, gA + (size_t)row * K_ + cg * 4);
            cp16(dB + (row * GP + cg * 4) * 4, gB + (size_t)row * K_ + cg * 4);
        }
        cp_commit();
    };

    issue(0);
    issue(1);

    for (int kc = 0; kc < nk; kc++) {
        cp_wait1();
        __syncthreads();

        const float* sA = sm + (kc % GSTAGES) * STAGE_F;
        const float* sB = sA + 128 * GP;

        #pragma unroll
        for (int ks = 0; ks < 4; ks++) {
            const int k0 = ks * 8;
            float af[4][4], bf[4][2];
            #pragma unroll
            for (int mt = 0; mt < 4; mt++) {
                const int row = wm + mt * 16 + r8;
                af[mt][0] = sA[row * GP + k0 + c4];
                af[mt][1] = sA[(row + 8) * GP + k0 + c4];
                af[mt][2] = sA[row * GP + k0 + c4 + 4];
                af[mt][3] = sA[(row + 8) * GP + k0 + c4 + 4];
            }
            #pragma unroll
            for (int nt = 0; nt < 4; nt++) {
                const int col = wn + nt * 8 + r8;
                bf[nt][0] = sB[col * GP + k0 + c4];
                bf[nt][1] = sB[col * GP + k0 + c4 + 4];
            }
            #pragma unroll
            for (int mt = 0; mt < 4; mt++)
                #pragma unroll
                for (int nt = 0; nt < 4; nt++)
                    mma_tf32(acc[mt][nt], af[mt], bf[nt]);
        }
        __syncthreads();
        if (kc + 2 < nk) issue(kc + 2);
    }

    #pragma unroll
    for (int mt = 0; mt < 4; mt++) {
        const int row = bm + wm + mt * 16 + r8;
        #pragma unroll
        for (int nt = 0; nt < 4; nt++) {
            const int col = bn + wn + nt * 8 + 2 * c4;
            *(float2*)&C[(size_t)row * N + col] =
                make_float2(acc[mt][nt][0], acc[mt][nt][1]);
            *(float2*)&C[(size_t)(row + 8) * N + col] =
                make_float2(acc[mt][nt][2], acc[mt][nt][3]);
        }
    }
}

// =====================================================================
// fp32 FFMA NT GEMM (R1, known good): V projection + output projection
// =====================================================================
__global__ __launch_bounds__(256) void gemm_nt_kernel(
    const float* __restrict__ A, const float* __restrict__ Bm,
    float* __restrict__ C, int M, int N, int K_)
{
    __shared__ float As[16][128];
    __shared__ float Bs[16][128];

    const int tid = threadIdx.x;
    const int tx = tid & 15;
    const int ty = tid >> 4;
    const int bm = blockIdx.y * 128;
    const int bn = blockIdx.x * 128;
    const int r  = tid & 63;
    const int c4 = tid >> 6;

    float acc[8][8] = {};

    const float* Ar0 = A  + (size_t)(bm + r)      * K_ + c4 * 4;
    const float* Ar1 = A  + (size_t)(bm + r + 64) * K_ + c4 * 4;
    const float* Br0 = Bm + (size_t)(bn + r)      * K_ + c4 * 4;
    const float* Br1 = Bm + (size_t)(bn + r + 64) * K_ + c4 * 4;

    for (int k0 = 0; k0 < K_; k0 += 16) {
        float4 a0 = *(const float4*)(Ar0 + k0);
        float4 a1 = *(const float4*)(Ar1 + k0);
        float4 b0 = *(const float4*)(Br0 + k0);
        float4 b1 = *(const float4*)(Br1 + k0);
        __syncthreads();
        As[c4*4+0][r]    = a0.x; As[c4*4+1][r]    = a0.y;
        As[c4*4+2][r]    = a0.z; As[c4*4+3][r]    = a0.w;
        As[c4*4+0][r+64] = a1.x; As[c4*4+1][r+64] = a1.y;
        As[c4*4+2][r+64] = a1.z; As[c4*4+3][r+64] = a1.w;
        Bs[c4*4+0][r]    = b0.x; Bs[c4*4+1][r]    = b0.y;
        Bs[c4*4+2][r]    = b0.z; Bs[c4*4+3][r]    = b0.w;
        Bs[c4*4+0][r+64] = b1.x; Bs[c4*4+1][r+64] = b1.y;
        Bs[c4*4+2][r+64] = b1.z; Bs[c4*4+3][r+64] = b1.w;
        __syncthreads();

        #pragma unroll
        for (int kk = 0; kk < 16; kk++) {
            float av[8], bv[8];
            *(float4*)(av)     = *(const float4*)&As[kk][ty * 4];
            *(float4*)(av + 4) = *(const float4*)&As[kk][64 + ty * 4];
            *(float4*)(bv)     = *(const float4*)&Bs[kk][tx * 4];
            *(float4*)(bv + 4) = *(const float4*)&Bs[kk][64 + tx * 4];
            #pragma unroll
            for (int i = 0; i < 8; i++)
                #pragma unroll
                for (int j = 0; j < 8; j++)
                    acc[i][j] += av[i] * bv[j];
        }
    }

    #pragma unroll
    for (int i = 0; i < 8; i++) {
        int row = bm + ((i < 4) ? (ty * 4 + i) : (64 + ty * 4 + i - 4));
        float* Cp = C + (size_t)row * N + bn;
        *(float4*)(Cp + tx * 4)      = make_float4(acc[i][0], acc[i][1], acc[i][2], acc[i][3]);
        *(float4*)(Cp + 64 + tx * 4) = make_float4(acc[i][4], acc[i][5], acc[i][6], acc[i][7]);
    }
}

// =====================================================================
// Flash attention: S = QK^T via tf32 mma.sync (softmax-attenuated error),
// online softmax + PV in fp32 FFMA (precision-critical path).
// smem: Qs[64][68], Ks[64][68] (tf32, row-major), Vs[64][68], Ps[64][68]
// =====================================================================
#define FP 68
#define FLASH_SMEM (4 * 64 * FP * 4)

__global__ __launch_bounds__(256) void flash_kernel()
{
    extern __shared__ float fsm[];
    float* Qs = fsm;                 // [64][FP] (q, d)  tf32-rounded, scaled
    float* Ks = fsm + 64 * FP;       // [64][FP] (kv, d) tf32-rounded
    float* Vs = fsm + 2 * 64 * FP;   // [64][FP] (kv, d) fp32
    float* Ps = fsm + 3 * 64 * FP;   // [64][FP] scores -> probs

    const int tid  = threadIdx.x;
    const int lane = tid & 31;
    const int wid  = tid >> 5;
    const int r8   = lane >> 2;
    const int c4   = lane & 3;
    const int wm   = (wid & 3) * 16;   // mma m-group (4 groups x 16 rows)
    const int wn   = (wid >> 2) * 32;  // mma n-half  (2 halves x 32 cols)
    const int tx   = tid & 15;
    const int ty   = tid >> 4;
    const int r    = tid & 63;
    const int cg   = tid >> 6;
    const int bh   = blockIdx.y;
    const int b    = bh >> 4, h = bh & 15;
    const int q0   = blockIdx.x * 64;

    const float* Qh = g_Q + (size_t)bh * (SQ * HD);
    const float* Kh = g_K + (size_t)bh * (SKV * HD);
    const float* Vh = g_V + (size_t)bh * (SKV * HD);

    // Q tile -> Qs row-major, scaled by 1/HD, tf32-rounded
    const float qsc = 1.0f / (float)HD;
    #pragma unroll
    for (int it = 0; it < 4; it++) {
        int idx = tid + it * 256;         // 0..1023
        int row = idx >> 4, cc = idx & 15;
        float4 q = *(const float4*)(Qh + (size_t)(q0 + row) * HD + cc * 4);
        *(float4*)&Qs[row * FP + cc * 4] = make_float4(
            rna_tf32(q.x * qsc), rna_tf32(q.y * qsc),
            rna_tf32(q.z * qsc), rna_tf32(q.w * qsc));
    }

    float m_i[4], l_i[4], o[4][4];
    #pragma unroll
    for (int i = 0; i < 4; i++) {
        m_i[i] = -INFINITY; l_i[i] = 0.0f;
        #pragma unroll
        for (int j = 0; j < 4; j++) o[i][j] = 0.0f;
    }

    for (int kc = 0; kc < SKV / 64; kc++) {
        const int n0 = kc * 64;
        float4 kv[4], vv[4];
        #pragma unroll
        for (int it = 0; it < 4; it++) {
            int cc = cg + it * 4;
            kv[it] = *(const float4*)(Kh + (size_t)(n0 + r) * HD + cc * 4);
            vv[it] = *(const float4*)(Vh + (size_t)(n0 + r) * HD + cc * 4);
        }
        __syncthreads();   // prior chunk: mma reads of Ks, PV reads of Vs done
        #pragma unroll
        for (int it = 0; it < 4; it++) {
            int cc = cg + it * 4;
            *(float4*)&Ks[r * FP + cc * 4] = make_float4(
                rna_tf32(kv[it].x), rna_tf32(kv[it].y),
                rna_tf32(kv[it].z), rna_tf32(kv[it].w));
            *(float4*)&Vs[r * FP + cc * 4] = vv[it];
        }
        __syncthreads();

        // ---- S = Q K^T via tf32 mma: warp covers m16 x n32, K=64 = 8 k8 ----
        float sf[4][4] = {};
        #pragma unroll
        for (int ks = 0; ks < 8; ks++) {
            const int k0 = ks * 8;
            float af[4];
            af[0] = Qs[(wm + r8) * FP + k0 + c4];
            af[1] = Qs[(wm + r8 + 8) * FP + k0 + c4];
            af[2] = Qs[(wm + r8) * FP + k0 + c4 + 4];
            af[3] = Qs[(wm + r8 + 8) * FP + k0 + c4 + 4];
            #pragma unroll
            for (int nt = 0; nt < 4; nt++) {
                float bf[2];
                bf[0] = Ks[(wn + nt * 8 + r8) * FP + k0 + c4];
                bf[1] = Ks[(wn + nt * 8 + r8) * FP + k0 + c4 + 4];
                mma_tf32(sf[nt], af, bf);
            }
        }
        // scatter S fragments to Ps
        #pragma unroll
        for (int nt = 0; nt < 4; nt++) {
            const int col = wn + nt * 8 + 2 * c4;
            *(float2*)&Ps[(wm + r8) * FP + col]     = make_float2(sf[nt][0], sf[nt][1]);
            *(float2*)&Ps[(wm + r8 + 8) * FP + col] = make_float2(sf[nt][2], sf[nt][3]);
        }
        __syncthreads();

        // ---- online softmax (fp32), thread owns rows ty*4..+3, cols tx*4..+3 ----
        #pragma unroll
        for (int ri = 0; ri < 4; ri++) {
            float4 sv = *(const float4*)&Ps[(ty * 4 + ri) * FP + tx * 4];
            float s0 = sv.x, s1 = sv.y, s2 = sv.z, s3 = sv.w;
            float mx = fmaxf(fmaxf(s0, s1), fmaxf(s2, s3));
            #pragma unroll
            for (int off = 1; off < 16; off <<= 1)
                mx = fmaxf(mx, __shfl_xor_sync(0xffffffffu, mx, off));
            float mnew = fmaxf(m_i[ri], mx);
            float corr = __expf(m_i[ri] - mnew);
            s0 = __expf(s0 - mnew); s1 = __expf(s1 - mnew);
            s2 = __expf(s2 - mnew); s3 = __expf(s3 - mnew);
            float sum = s0 + s1 + s2 + s3;
            #pragma unroll
            for (int off = 1; off < 16; off <<= 1)
                sum += __shfl_xor_sync(0xffffffffu, sum, off);
            l_i[ri] = l_i[ri] * corr + sum;
            m_i[ri] = mnew;
            #pragma unroll
            for (int j = 0; j < 4; j++) o[ri][j] *= corr;
            *(float4*)&Ps[(ty * 4 + ri) * FP + tx * 4] = make_float4(s0, s1, s2, s3);
        }
        __syncthreads();

        // ---- O += P V (fp32 FFMA) ----
        #pragma unroll 8
        for (int k = 0; k < 64; k++) {
            float4 v = *(const float4*)&Vs[k * FP + tx * 4];
            #pragma unroll
            for (int ri = 0; ri < 4; ri++) {
                float p = Ps[(ty * 4 + ri) * FP + k];
                o[ri][0] += p * v.x; o[ri][1] += p * v.y;
                o[ri][2] += p * v.z; o[ri][3] += p * v.w;
            }
        }
    }

    // epilogue: AO[b, s', h*64 + d'] (fp32; output projection is fp32 FFMA)
    float* AOp = g_AO + (size_t)b * (SQ * DQ_) + h * HD;
    #pragma unroll
    for (int ri = 0; ri < 4; ri++) {
        float inv = 1.0f / l_i[ri];
        int srow = q0 + ty * 4 + ri;
        *(float4*)&AOp[(size_t)srow * DQ_ + tx * 4] = make_float4(
            o[ri][0] * inv, o[ri][1] * inv, o[ri][2] * inv, o[ri][3] * inv);
    }
}

// =====================================================================
// launch
// =====================================================================
static inline void launch_round(const float* in, float* out, int n) {
    int n4 = n / 4;
    round_kernel<<<(n4 + 255) / 256, 256>>>((const float4*)in, (float4*)out, n4);
}

extern "C" void kernel_launch(void* const* d_in, const int* in_sizes, int n_in,
                              void* d_out, int out_size)
{
    (void)in_sizes; (void)n_in; (void)out_size;
    const float* x_q  = (const float*)d_in[0];
    const float* x_kv = (const float*)d_in[1];
    const float* Wq   = (const float*)d_in[2];
    const float* Wk   = (const float*)d_in[3];
    const float* Wv   = (const float*)d_in[4];
    const float* Wo   = (const float*)d_in[5];
    float* out = (float*)d_out;

    float *Q, *K, *V, *AO, *xq, *xkv, *wq, *wk;
    cudaGetSymbolAddress((void**)&Q,   g_Q);
    cudaGetSymbolAddress((void**)&K,   g_K);
    cudaGetSymbolAddress((void**)&V,   g_V);
    cudaGetSymbolAddress((void**)&AO,  g_AO);
    cudaGetSymbolAddress((void**)&xq,  g_xq);
    cudaGetSymbolAddress((void**)&xkv, g_xkv);
    cudaGetSymbolAddress((void**)&wq,  g_wq);
    cudaGetSymbolAddress((void**)&wk,  g_wk);

    cudaFuncSetAttribute(gemm_mma, cudaFuncAttributeMaxDynamicSharedMemorySize, GEMM_SMEM);
    cudaFuncSetAttribute(flash_kernel, cudaFuncAttributeMaxDynamicSharedMemorySize, FLASH_SMEM);

    // tf32-RNA prepass (Q/K projection operands only)
    launch_round(x_q,  xq,  BB * SQ * DQ_);
    launch_round(x_kv, xkv, BB * SKV * DKV_);
    launch_round(Wq, wq, DQ_ * DQ_);
    launch_round(Wk, wk, DQ_ * DKV_);

    // Q = x_q @ Wq^T  (tf32 tensor — error attenuated through softmax)
    gemm_mma<<<dim3(DQ_ / 128, (BB * SQ) / 128),  256, GEMM_SMEM>>>(xq,  wq, Q, BB * SQ,  DQ_, DQ_);
    // K = x_kv @ Wk^T (tf32 tensor)
    gemm_mma<<<dim3(DQ_ / 128, (BB * SKV) / 128), 256, GEMM_SMEM>>>(xkv, wk, K, BB * SKV, DQ_, DKV_);
    // V = x_kv @ Wv^T (fp32 — precision-critical path)
    gemm_nt_kernel<<<dim3(DQ_ / 128, (BB * SKV) / 128), 256>>>(x_kv, Wv, V, BB * SKV, DQ_, DKV_);
    // attention (S via tf32 mma, softmax+PV fp32)
    flash_kernel<<<dim3(SQ / 64, BB * NH), 256, FLASH_SMEM>>>();
    // out = AO @ Wo^T (fp32 — precision-critical path)
    gemm_nt_kernel<<<dim3(DQ_ / 128, (BB * SQ) / 128), 256>>>(AO, Wo, out, BB * SQ, DQ_, DQ_);
}

// round 6
// speedup vs baseline: 1.5669x; 1.1900x over previous
#include <cuda_runtime.h>
#include <cuda_bf16.h>
#include <math.h>
#include <cstdint>

// ---------------- problem constants ----------------
#define BB   2
#define SQ   1024
#define SKV  4096
#define DQ_  1024
#define DKV_ 768
#define NH   16
#define HD   64

// ---------------- scratch ----------------
__device__ float g_Q [BB * SQ  * DQ_];
__device__ float g_K [BB * SKV * DQ_];
__device__ float g_V [BB * SKV * DQ_];
__device__ float g_AO[BB * SQ  * DQ_];
// tf32-rounded operand copies (Q/K projection path)
__device__ float g_xq [BB * SQ  * DQ_];
__device__ float g_xkv[BB * SKV * DKV_];
__device__ float g_wq [DQ_ * DQ_];
__device__ float g_wk [DQ_ * DKV_];
// bf16 hi/lo splits (V projection + output projection paths)
__device__ __align__(256) __nv_bfloat16 g_xkv_h[BB * SKV * DKV_];
__device__ __align__(256) __nv_bfloat16 g_xkv_l[BB * SKV * DKV_];
__device__ __align__(256) __nv_bfloat16 g_wv_h [DQ_ * DKV_];
__device__ __align__(256) __nv_bfloat16 g_wv_l [DQ_ * DKV_];
__device__ __align__(256) __nv_bfloat16 g_ao_h [BB * SQ * DQ_];
__device__ __align__(256) __nv_bfloat16 g_ao_l [BB * SQ * DQ_];
__device__ __align__(256) __nv_bfloat16 g_wo_h [DQ_ * DQ_];
__device__ __align__(256) __nv_bfloat16 g_wo_l [DQ_ * DQ_];

// =====================================================================
// helpers
// =====================================================================
__device__ __forceinline__ uint32_t smem_u32(const void* p) {
    uint32_t a;
    asm("{ .reg .u64 t; cvta.to.shared.u64 t, %1; cvt.u32.u64 %0, t; }" : "=r"(a) : "l"(p));
    return a;
}
__device__ __forceinline__ float rna_tf32(float x) {
    uint32_t r;
    asm("cvt.rna.tf32.f32 %0, %1;" : "=r"(r) : "f"(x));
    return __uint_as_float(r);
}
__device__ __forceinline__ void cp16(uint32_t dst, const void* src) {
    asm volatile("cp.async.cg.shared.global [%0], [%1], 16;" :: "r"(dst), "l"(src) : "memory");
}
__device__ __forceinline__ void cp_commit() {
    asm volatile("cp.async.commit_group;" ::: "memory");
}
__device__ __forceinline__ void cp_wait1() {
    asm volatile("cp.async.wait_group 1;" ::: "memory");
}

// tf32 m16n8k8: D += A * B^T
__device__ __forceinline__ void mma_tf32(float* d, const float* a, const float* b) {
    asm volatile(
        "mma.sync.aligned.m16n8k8.row.col.f32.tf32.tf32.f32 "
        "{%0,%1,%2,%3}, {%4,%5,%6,%7}, {%8,%9}, {%0,%1,%2,%3};"
        : "+f"(d[0]), "+f"(d[1]), "+f"(d[2]), "+f"(d[3])
        : "r"(__float_as_uint(a[0])), "r"(__float_as_uint(a[1])),
          "r"(__float_as_uint(a[2])), "r"(__float_as_uint(a[3])),
          "r"(__float_as_uint(b[0])), "r"(__float_as_uint(b[1])));
}

// bf16 m16n8k16: D += A * B^T  (a = 4 packed uint32, b = 2 packed uint32)
__device__ __forceinline__ void mma_bf16(float* d, const uint32_t* a, const uint32_t* b) {
    asm volatile(
        "mma.sync.aligned.m16n8k16.row.col.f32.bf16.bf16.f32 "
        "{%0,%1,%2,%3}, {%4,%5,%6,%7}, {%8,%9}, {%0,%1,%2,%3};"
        : "+f"(d[0]), "+f"(d[1]), "+f"(d[2]), "+f"(d[3])
        : "r"(a[0]), "r"(a[1]), "r"(a[2]), "r"(a[3]),
          "r"(b[0]), "r"(b[1]));
}

// =====================================================================
// prepass kernels
// =====================================================================
__global__ void round_kernel(const float4* __restrict__ in, float4* __restrict__ out, int n4) {
    int i = blockIdx.x * blockDim.x + threadIdx.x;
    if (i < n4) {
        float4 v = in[i];
        v.x = rna_tf32(v.x); v.y = rna_tf32(v.y);
        v.z = rna_tf32(v.z); v.w = rna_tf32(v.w);
        out[i] = v;
    }
}

// fp32 -> bf16 hi + bf16 lo (lo = bf16(x - hi))
__global__ void split_kernel(const float2* __restrict__ in,
                             __nv_bfloat162* __restrict__ hi,
                             __nv_bfloat162* __restrict__ lo, int n2) {
    int i = blockIdx.x * blockDim.x + threadIdx.x;
    if (i < n2) {
        float2 v = in[i];
        __nv_bfloat16 hx = __float2bfloat16_rn(v.x);
        __nv_bfloat16 hy = __float2bfloat16_rn(v.y);
        __nv_bfloat16 lx = __float2bfloat16_rn(v.x - __bfloat162float(hx));
        __nv_bfloat16 ly = __float2bfloat16_rn(v.y - __bfloat162float(hy));
        hi[i] = __nv_bfloat162{hx, hy};
        lo[i] = __nv_bfloat162{lx, ly};
    }
}

// =====================================================================
// tf32 mma.sync NT GEMM (Q/K projections) — unchanged, validated
// =====================================================================
#define GP        36
#define STAGE_F   (2 * 128 * GP)
#define GSTAGES   3
#define GEMM_SMEM (GSTAGES * STAGE_F * 4)

__global__ __launch_bounds__(256) void gemm_mma(
    const float* __restrict__ A, const float* __restrict__ B,
    float* __restrict__ C, int M, int N, int K_)
{
    extern __shared__ float sm[];
    const uint32_t sb = smem_u32(sm);

    const int tid  = threadIdx.x;
    const int wid  = tid >> 5;
    const int lane = tid & 31;
    const int r8   = lane >> 2;
    const int c4   = lane & 3;
    const int wm   = (wid & 1) * 64;
    const int wn   = (wid >> 1) * 32;
    const int bm   = blockIdx.y * 128;
    const int bn   = blockIdx.x * 128;
    const int nk   = K_ >> 5;

    float acc[4][4][4];
    #pragma unroll
    for (int mt = 0; mt < 4; mt++)
        #pragma unroll
        for (int nt = 0; nt < 4; nt++)
            #pragma unroll
            for (int j = 0; j < 4; j++) acc[mt][nt][j] = 0.0f;

    auto issue = [&](int kc) {
        const int s = kc % GSTAGES;
        const uint32_t dA = sb + (uint32_t)(s * STAGE_F) * 4;
        const uint32_t dB = dA + 128 * GP * 4;
        const float* gA = A + (size_t)bm * K_ + kc * 32;
        const float* gB = B + (size_t)bn * K_ + kc * 32;
        #pragma unroll
        for (int i = 0; i < 4; i++) {
            const int idx = tid + 256 * i;
            const int row = idx >> 3, cg = idx & 7;
            cp16(dA + (row * GP + cg * 4) * 4, gA + (size_t)row * K_ + cg * 4);
            cp16(dB + (row * GP + cg * 4) * 4, gB + (size_t)row * K_ + cg * 4);
        }
        cp_commit();
    };

    issue(0);
    issue(1);

    for (int kc = 0; kc < nk; kc++) {
        cp_wait1();
        __syncthreads();

        const float* sA = sm + (kc % GSTAGES) * STAGE_F;
        const float* sB = sA + 128 * GP;

        #pragma unroll
        for (int ks = 0; ks < 4; ks++) {
            const int k0 = ks * 8;
            float af[4][4], bf[4][2];
            #pragma unroll
            for (int mt = 0; mt < 4; mt++) {
                const int row = wm + mt * 16 + r8;
                af[mt][0] = sA[row * GP + k0 + c4];
                af[mt][1] = sA[(row + 8) * GP + k0 + c4];
                af[mt][2] = sA[row * GP + k0 + c4 + 4];
                af[mt][3] = sA[(row + 8) * GP + k0 + c4 + 4];
            }
            #pragma unroll
            for (int nt = 0; nt < 4; nt++) {
                const int col = wn + nt * 8 + r8;
                bf[nt][0] = sB[col * GP + k0 + c4];
                bf[nt][1] = sB[col * GP + k0 + c4 + 4];
            }
            #pragma unroll
            for (int mt = 0; mt < 4; mt++)
                #pragma unroll
                for (int nt = 0; nt < 4; nt++)
                    mma_tf32(acc[mt][nt], af[mt], bf[nt]);
        }
        __syncthreads();
        if (kc + 2 < nk) issue(kc + 2);
    }

    #pragma unroll
    for (int mt = 0; mt < 4; mt++) {
        const int row = bm + wm + mt * 16 + r8;
        #pragma unroll
        for (int nt = 0; nt < 4; nt++) {
            const int col = bn + wn + nt * 8 + 2 * c4;
            *(float2*)&C[(size_t)row * N + col] =
                make_float2(acc[mt][nt][0], acc[mt][nt][1]);
            *(float2*)&C[(size_t)(row + 8) * N + col] =
                make_float2(acc[mt][nt][2], acc[mt][nt][3]);
        }
    }
}

// =====================================================================
// bf16x3 compensated NT GEMM: C = A*B^T with A = Ah+Al, B = Bh+Bl (bf16)
// C ~= Ah*Bh + Ah*Bl + Al*Bh  (fp32 accumulate) — near-fp32 precision.
// CTA 128x128, BK=32 (2 x k16), 3-stage cp.async, 256 threads.
// smem per stage: 4 arrays (Ah, Al, Bh, Bl) of 128 rows x 16 words,
// pitch 20 words -> conflict-free fragment loads.
// =====================================================================
#define BP        20                        // pitch in uint32 words
#define BSTAGE_U  (4 * 128 * BP)            // words per stage
#define B3STAGES  3
#define B3_SMEM   (B3STAGES * BSTAGE_U * 4) // 122880 bytes

__global__ __launch_bounds__(256) void gemm_bf3(
    const __nv_bfloat16* __restrict__ Ah, const __nv_bfloat16* __restrict__ Al,
    const __nv_bfloat16* __restrict__ Bh, const __nv_bfloat16* __restrict__ Bl,
    float* __restrict__ C, int M, int N, int K_)
{
    extern __shared__ uint32_t smu[];
    const uint32_t sb = smem_u32(smu);

    const int tid  = threadIdx.x;
    const int wid  = tid >> 5;
    const int lane = tid & 31;
    const int r8   = lane >> 2;
    const int c4   = lane & 3;
    const int wm   = (wid & 1) * 64;
    const int wn   = (wid >> 1) * 32;
    const int bm   = blockIdx.y * 128;
    const int bn   = blockIdx.x * 128;
    const int nk   = K_ >> 5;               // K chunks of 32 bf16

    float acc[4][4][4];
    #pragma unroll
    for (int mt = 0; mt < 4; mt++)
        #pragma unroll
        for (int nt = 0; nt < 4; nt++)
            #pragma unroll
            for (int j = 0; j < 4; j++) acc[mt][nt][j] = 0.0f;

    // one chunk = 128 rows x 32 bf16 per array; 4 cp16 per row per array
    auto issue = [&](int kc) {
        const int s = kc % B3STAGES;
        const uint32_t base = sb + (uint32_t)(s * BSTAGE_U) * 4;
        const __nv_bfloat16* gsrc[4] = {
            Ah + (size_t)bm * K_ + kc * 32, Al + (size_t)bm * K_ + kc * 32,
            Bh + (size_t)bn * K_ + kc * 32, Bl + (size_t)bn * K_ + kc * 32 };
        #pragma unroll
        for (int i = 0; i < 8; i++) {
            const int idx = tid + 256 * i;     // 0..2047
            const int arr = idx >> 9;          // 0..3
            const int rem = idx & 511;
            const int row = rem >> 2, cg = rem & 3;   // 128 rows x 4 chunks
            cp16(base + (uint32_t)(arr * 128 * BP + row * BP + cg * 4) * 4,
                 gsrc[arr] + (size_t)row * K_ + cg * 8);
        }
        cp_commit();
    };

    issue(0);
    issue(1);

    for (int kc = 0; kc < nk; kc++) {
        cp_wait1();
        __syncthreads();

        const uint32_t* sAh = smu + (kc % B3STAGES) * BSTAGE_U;
        const uint32_t* sAl = sAh + 128 * BP;
        const uint32_t* sBh = sAl + 128 * BP;
        const uint32_t* sBl = sBh + 128 * BP;

        #pragma unroll
        for (int ks = 0; ks < 2; ks++) {       // two k16 steps per chunk
            const int w0 = ks * 8;
            uint32_t ah[4][4], al[4][4], bh[4][2], bl[4][2];
            #pragma unroll
            for (int mt = 0; mt < 4; mt++) {
                const int row = wm + mt * 16 + r8;
                ah[mt][0] = sAh[row * BP + w0 + c4];
                ah[mt][1] = sAh[(row + 8) * BP + w0 + c4];
                ah[mt][2] = sAh[row * BP + w0 + c4 + 4];
                ah[mt][3] = sAh[(row + 8) * BP + w0 + c4 + 4];
                al[mt][0] = sAl[row * BP + w0 + c4];
                al[mt][1] = sAl[(row + 8) * BP + w0 + c4];
                al[mt][2] = sAl[row * BP + w0 + c4 + 4];
                al[mt][3] = sAl[(row + 8) * BP + w0 + c4 + 4];
            }
            #pragma unroll
            for (int nt = 0; nt < 4; nt++) {
                const int col = wn + nt * 8 + r8;
                bh[nt][0] = sBh[col * BP + w0 + c4];
                bh[nt][1] = sBh[col * BP + w0 + c4 + 4];
                bl[nt][0] = sBl[col * BP + w0 + c4];
                bl[nt][1] = sBl[col * BP + w0 + c4 + 4];
            }
            #pragma unroll
            for (int mt = 0; mt < 4; mt++)
                #pragma unroll
                for (int nt = 0; nt < 4; nt++) {
                    mma_bf16(acc[mt][nt], ah[mt], bh[nt]);
                    mma_bf16(acc[mt][nt], ah[mt], bl[nt]);
                    mma_bf16(acc[mt][nt], al[mt], bh[nt]);
                }
        }
        __syncthreads();
        if (kc + 2 < nk) issue(kc + 2);
    }

    #pragma unroll
    for (int mt = 0; mt < 4; mt++) {
        const int row = bm + wm + mt * 16 + r8;
        #pragma unroll
        for (int nt = 0; nt < 4; nt++) {
            const int col = bn + wn + nt * 8 + 2 * c4;
            *(float2*)&C[(size_t)row * N + col] =
                make_float2(acc[mt][nt][0], acc[mt][nt][1]);
            *(float2*)&C[(size_t)(row + 8) * N + col] =
                make_float2(acc[mt][nt][2], acc[mt][nt][3]);
        }
    }
}

// =====================================================================
// Flash attention: S via tf32 mma, softmax + PV fp32 — unchanged (R5)
// =====================================================================
#define FP 68
#define FLASH_SMEM (4 * 64 * FP * 4)

__global__ __launch_bounds__(256) void flash_kernel()
{
    extern __shared__ float fsm[];
    float* Qs = fsm;
    float* Ks = fsm + 64 * FP;
    float* Vs = fsm + 2 * 64 * FP;
    float* Ps = fsm + 3 * 64 * FP;

    const int tid  = threadIdx.x;
    const int lane = tid & 31;
    const int wid  = tid >> 5;
    const int r8   = lane >> 2;
    const int c4   = lane & 3;
    const int wm   = (wid & 3) * 16;
    const int wn   = (wid >> 2) * 32;
    const int tx   = tid & 15;
    const int ty   = tid >> 4;
    const int r    = tid & 63;
    const int cg   = tid >> 6;
    const int bh   = blockIdx.y;
    const int b    = bh >> 4, h = bh & 15;
    const int q0   = blockIdx.x * 64;

    const float* Qh = g_Q + (size_t)bh * (SQ * HD);
    const float* Kh = g_K + (size_t)bh * (SKV * HD);
    const float* Vh = g_V + (size_t)bh * (SKV * HD);

    const float qsc = 1.0f / (float)HD;
    #pragma unroll
    for (int it = 0; it < 4; it++) {
        int idx = tid + it * 256;
        int row = idx >> 4, cc = idx & 15;
        float4 q = *(const float4*)(Qh + (size_t)(q0 + row) * HD + cc * 4);
        *(float4*)&Qs[row * FP + cc * 4] = make_float4(
            rna_tf32(q.x * qsc), rna_tf32(q.y * qsc),
            rna_tf32(q.z * qsc), rna_tf32(q.w * qsc));
    }

    float m_i[4], l_i[4], o[4][4];
    #pragma unroll
    for (int i = 0; i < 4; i++) {
        m_i[i] = -INFINITY; l_i[i] = 0.0f;
        #pragma unroll
        for (int j = 0; j < 4; j++) o[i][j] = 0.0f;
    }

    for (int kc = 0; kc < SKV / 64; kc++) {
        const int n0 = kc * 64;
        float4 kv[4], vv[4];
        #pragma unroll
        for (int it = 0; it < 4; it++) {
            int cc = cg + it * 4;
            kv[it] = *(const float4*)(Kh + (size_t)(n0 + r) * HD + cc * 4);
            vv[it] = *(const float4*)(Vh + (size_t)(n0 + r) * HD + cc * 4);
        }
        __syncthreads();
        #pragma unroll
        for (int it = 0; it < 4; it++) {
            int cc = cg + it * 4;
            *(float4*)&Ks[r * FP + cc * 4] = make_float4(
                rna_tf32(kv[it].x), rna_tf32(kv[it].y),
                rna_tf32(kv[it].z), rna_tf32(kv[it].w));
            *(float4*)&Vs[r * FP + cc * 4] = vv[it];
        }
        __syncthreads();

        float sf[4][4] = {};
        #pragma unroll
        for (int ks = 0; ks < 8; ks++) {
            const int k0 = ks * 8;
            float af[4];
            af[0] = Qs[(wm + r8) * FP + k0 + c4];
            af[1] = Qs[(wm + r8 + 8) * FP + k0 + c4];
            af[2] = Qs[(wm + r8) * FP + k0 + c4 + 4];
            af[3] = Qs[(wm + r8 + 8) * FP + k0 + c4 + 4];
            #pragma unroll
            for (int nt = 0; nt < 4; nt++) {
                float bf[2];
                bf[0] = Ks[(wn + nt * 8 + r8) * FP + k0 + c4];
                bf[1] = Ks[(wn + nt * 8 + r8) * FP + k0 + c4 + 4];
                mma_tf32(sf[nt], af, bf);
            }
        }
        #pragma unroll
        for (int nt = 0; nt < 4; nt++) {
            const int col = wn + nt * 8 + 2 * c4;
            *(float2*)&Ps[(wm + r8) * FP + col]     = make_float2(sf[nt][0], sf[nt][1]);
            *(float2*)&Ps[(wm + r8 + 8) * FP + col] = make_float2(sf[nt][2], sf[nt][3]);
        }
        __syncthreads();

        #pragma unroll
        for (int ri = 0; ri < 4; ri++) {
            float4 sv = *(const float4*)&Ps[(ty * 4 + ri) * FP + tx * 4];
            float s0 = sv.x, s1 = sv.y, s2 = sv.z, s3 = sv.w;
            float mx = fmaxf(fmaxf(s0, s1), fmaxf(s2, s3));
            #pragma unroll
            for (int off = 1; off < 16; off <<= 1)
                mx = fmaxf(mx, __shfl_xor_sync(0xffffffffu, mx, off));
            float mnew = fmaxf(m_i[ri], mx);
            float corr = __expf(m_i[ri] - mnew);
            s0 = __expf(s0 - mnew); s1 = __expf(s1 - mnew);
            s2 = __expf(s2 - mnew); s3 = __expf(s3 - mnew);
            float sum = s0 + s1 + s2 + s3;
            #pragma unroll
            for (int off = 1; off < 16; off <<= 1)
                sum += __shfl_xor_sync(0xffffffffu, sum, off);
            l_i[ri] = l_i[ri] * corr + sum;
            m_i[ri] = mnew;
            #pragma unroll
            for (int j = 0; j < 4; j++) o[ri][j] *= corr;
            *(float4*)&Ps[(ty * 4 + ri) * FP + tx * 4] = make_float4(s0, s1, s2, s3);
        }
        __syncthreads();

        #pragma unroll 8
        for (int k = 0; k < 64; k++) {
            float4 v = *(const float4*)&Vs[k * FP + tx * 4];
            #pragma unroll
            for (int ri = 0; ri < 4; ri++) {
                float p = Ps[(ty * 4 + ri) * FP + k];
                o[ri][0] += p * v.x; o[ri][1] += p * v.y;
                o[ri][2] += p * v.z; o[ri][3] += p * v.w;
            }
        }
    }

    float* AOp = g_AO + (size_t)b * (SQ * DQ_) + h * HD;
    #pragma unroll
    for (int ri = 0; ri < 4; ri++) {
        float inv = 1.0f / l_i[ri];
        int srow = q0 + ty * 4 + ri;
        *(float4*)&AOp[(size_t)srow * DQ_ + tx * 4] = make_float4(
            o[ri][0] * inv, o[ri][1] * inv, o[ri][2] * inv, o[ri][3] * inv);
    }
}

// =====================================================================
// launch
// =====================================================================
static inline void launch_round(const float* in, float* out, int n) {
    int n4 = n / 4;
    round_kernel<<<(n4 + 255) / 256, 256>>>((const float4*)in, (float4*)out, n4);
}
static inline void launch_split(const float* in, __nv_bfloat16* hi, __nv_bfloat16* lo, int n) {
    int n2 = n / 2;
    split_kernel<<<(n2 + 255) / 256, 256>>>((const float2*)in,
        (__nv_bfloat162*)hi, (__nv_bfloat162*)lo, n2);
}

extern "C" void kernel_launch(void* const* d_in, const int* in_sizes, int n_in,
                              void* d_out, int out_size)
{
    (void)in_sizes; (void)n_in; (void)out_size;
    const float* x_q  = (const float*)d_in[0];
    const float* x_kv = (const float*)d_in[1];
    const float* Wq   = (const float*)d_in[2];
    const float* Wk   = (const float*)d_in[3];
    const float* Wv   = (const float*)d_in[4];
    const float* Wo   = (const float*)d_in[5];
    float* out = (float*)d_out;

    float *Q, *K, *V, *AO, *xq, *xkv, *wq, *wk;
    __nv_bfloat16 *xkvh, *xkvl, *wvh, *wvl, *aoh, *aol, *woh, *wol;
    cudaGetSymbolAddress((void**)&Q,    g_Q);
    cudaGetSymbolAddress((void**)&K,    g_K);
    cudaGetSymbolAddress((void**)&V,    g_V);
    cudaGetSymbolAddress((void**)&AO,   g_AO);
    cudaGetSymbolAddress((void**)&xq,   g_xq);
    cudaGetSymbolAddress((void**)&xkv,  g_xkv);
    cudaGetSymbolAddress((void**)&wq,   g_wq);
    cudaGetSymbolAddress((void**)&wk,   g_wk);
    cudaGetSymbolAddress((void**)&xkvh, g_xkv_h);
    cudaGetSymbolAddress((void**)&xkvl, g_xkv_l);
    cudaGetSymbolAddress((void**)&wvh,  g_wv_h);
    cudaGetSymbolAddress((void**)&wvl,  g_wv_l);
    cudaGetSymbolAddress((void**)&aoh,  g_ao_h);
    cudaGetSymbolAddress((void**)&aol,  g_ao_l);
    cudaGetSymbolAddress((void**)&woh,  g_wo_h);
    cudaGetSymbolAddress((void**)&wol,  g_wo_l);

    cudaFuncSetAttribute(gemm_mma, cudaFuncAttributeMaxDynamicSharedMemorySize, GEMM_SMEM);
    cudaFuncSetAttribute(gemm_bf3, cudaFuncAttributeMaxDynamicSharedMemorySize, B3_SMEM);
    cudaFuncSetAttribute(flash_kernel, cudaFuncAttributeMaxDynamicSharedMemorySize, FLASH_SMEM);

    // prepasses
    launch_round(x_q,  xq,  BB * SQ * DQ_);
    launch_round(x_kv, xkv, BB * SKV * DKV_);
    launch_round(Wq, wq, DQ_ * DQ_);
    launch_round(Wk, wk, DQ_ * DKV_);
    launch_split(x_kv, xkvh, xkvl, BB * SKV * DKV_);
    launch_split(Wv,   wvh,  wvl,  DQ_ * DKV_);
    launch_split(Wo,   woh,  wol,  DQ_ * DQ_);

    // Q = x_q @ Wq^T  (tf32 — softmax-attenuated path)
    gemm_mma<<<dim3(DQ_ / 128, (BB * SQ) / 128),  256, GEMM_SMEM>>>(xq,  wq, Q, BB * SQ,  DQ_, DQ_);
    // K = x_kv @ Wk^T (tf32)
    gemm_mma<<<dim3(DQ_ / 128, (BB * SKV) / 128), 256, GEMM_SMEM>>>(xkv, wk, K, BB * SKV, DQ_, DKV_);
    // V = x_kv @ Wv^T (bf16x3 compensated — near-fp32 precision)
    gemm_bf3<<<dim3(DQ_ / 128, (BB * SKV) / 128), 256, B3_SMEM>>>(
        xkvh, xkvl, wvh, wvl, V, BB * SKV, DQ_, DKV_);
    // attention
    flash_kernel<<<dim3(SQ / 64, BB * NH), 256, FLASH_SMEM>>>();
    // split AO, then out = AO @ Wo^T (bf16x3 compensated)
    launch_split(AO, aoh, aol, BB * SQ * DQ_);
    gemm_bf3<<<dim3(DQ_ / 128, (BB * SQ) / 128), 256, B3_SMEM>>>(
        aoh, aol, woh, wol, out, BB * SQ, DQ_, DQ_);
}

// round 7
// speedup vs baseline: 1.9232x; 1.2274x over previous
#include <cuda_runtime.h>
#include <cuda_bf16.h>
#include <math.h>
#include <cstdint>

// ---------------- problem constants ----------------
#define BB   2
#define SQ   1024
#define SKV  4096
#define DQ_  1024
#define DKV_ 768
#define NH   16
#define HD   64

// ---------------- scratch ----------------
__device__ float g_Q [BB * SQ  * DQ_];
__device__ float g_K [BB * SKV * DQ_];
__device__ float g_V [BB * SKV * DQ_];
__device__ float g_AO[BB * SQ  * DQ_];
// tf32-rounded operand copies (Q/K projection path)
__device__ float g_xq [BB * SQ  * DQ_];
__device__ float g_xkv[BB * SKV * DKV_];
__device__ float g_wq [DQ_ * DQ_];
__device__ float g_wk [DQ_ * DKV_];
// bf16 hi/lo splits (V projection + output projection paths)
__device__ __align__(256) __nv_bfloat16 g_xkv_h[BB * SKV * DKV_];
__device__ __align__(256) __nv_bfloat16 g_xkv_l[BB * SKV * DKV_];
__device__ __align__(256) __nv_bfloat16 g_wv_h [DQ_ * DKV_];
__device__ __align__(256) __nv_bfloat16 g_wv_l [DQ_ * DKV_];
__device__ __align__(256) __nv_bfloat16 g_ao_h [BB * SQ * DQ_];
__device__ __align__(256) __nv_bfloat16 g_ao_l [BB * SQ * DQ_];
__device__ __align__(256) __nv_bfloat16 g_wo_h [DQ_ * DQ_];
__device__ __align__(256) __nv_bfloat16 g_wo_l [DQ_ * DQ_];

// =====================================================================
// helpers
// =====================================================================
__device__ __forceinline__ uint32_t smem_u32(const void* p) {
    uint32_t a;
    asm("{ .reg .u64 t; cvta.to.shared.u64 t, %1; cvt.u32.u64 %0, t; }" : "=r"(a) : "l"(p));
    return a;
}
__device__ __forceinline__ float rna_tf32(float x) {
    uint32_t r;
    asm("cvt.rna.tf32.f32 %0, %1;" : "=r"(r) : "f"(x));
    return __uint_as_float(r);
}
__device__ __forceinline__ void cp16(uint32_t dst, const void* src) {
    asm volatile("cp.async.cg.shared.global [%0], [%1], 16;" :: "r"(dst), "l"(src) : "memory");
}
__device__ __forceinline__ void cp_commit() {
    asm volatile("cp.async.commit_group;" ::: "memory");
}
__device__ __forceinline__ void cp_wait1() {
    asm volatile("cp.async.wait_group 1;" ::: "memory");
}
__device__ __forceinline__ uint32_t pack_bf16(__nv_bfloat16 a, __nv_bfloat16 b) {
    __nv_bfloat162 t{a, b};
    return *(uint32_t*)&t;
}

// tf32 m16n8k8: D += A * B^T
__device__ __forceinline__ void mma_tf32(float* d, const float* a, const float* b) {
    asm volatile(
        "mma.sync.aligned.m16n8k8.row.col.f32.tf32.tf32.f32 "
        "{%0,%1,%2,%3}, {%4,%5,%6,%7}, {%8,%9}, {%0,%1,%2,%3};"
        : "+f"(d[0]), "+f"(d[1]), "+f"(d[2]), "+f"(d[3])
        : "r"(__float_as_uint(a[0])), "r"(__float_as_uint(a[1])),
          "r"(__float_as_uint(a[2])), "r"(__float_as_uint(a[3])),
          "r"(__float_as_uint(b[0])), "r"(__float_as_uint(b[1])));
}

// bf16 m16n8k16: D += A * B^T
__device__ __forceinline__ void mma_bf16(float* d, const uint32_t* a, const uint32_t* b) {
    asm volatile(
        "mma.sync.aligned.m16n8k16.row.col.f32.bf16.bf16.f32 "
        "{%0,%1,%2,%3}, {%4,%5,%6,%7}, {%8,%9}, {%0,%1,%2,%3};"
        : "+f"(d[0]), "+f"(d[1]), "+f"(d[2]), "+f"(d[3])
        : "r"(a[0]), "r"(a[1]), "r"(a[2]), "r"(a[3]),
          "r"(b[0]), "r"(b[1]));
}

// =====================================================================
// prepass kernels
// =====================================================================
__global__ void round_kernel(const float4* __restrict__ in, float4* __restrict__ out, int n4) {
    int i = blockIdx.x * blockDim.x + threadIdx.x;
    if (i < n4) {
        float4 v = in[i];
        v.x = rna_tf32(v.x); v.y = rna_tf32(v.y);
        v.z = rna_tf32(v.z); v.w = rna_tf32(v.w);
        out[i] = v;
    }
}

__global__ void split_kernel(const float2* __restrict__ in,
                             __nv_bfloat162* __restrict__ hi,
                             __nv_bfloat162* __restrict__ lo, int n2) {
    int i = blockIdx.x * blockDim.x + threadIdx.x;
    if (i < n2) {
        float2 v = in[i];
        __nv_bfloat16 hx = __float2bfloat16_rn(v.x);
        __nv_bfloat16 hy = __float2bfloat16_rn(v.y);
        __nv_bfloat16 lx = __float2bfloat16_rn(v.x - __bfloat162float(hx));
        __nv_bfloat16 ly = __float2bfloat16_rn(v.y - __bfloat162float(hy));
        hi[i] = __nv_bfloat162{hx, hy};
        lo[i] = __nv_bfloat162{lx, ly};
    }
}

// =====================================================================
// tf32 mma.sync NT GEMM (Q/K projections) — validated
// =====================================================================
#define GP        36
#define STAGE_F   (2 * 128 * GP)
#define GSTAGES   3
#define GEMM_SMEM (GSTAGES * STAGE_F * 4)

__global__ __launch_bounds__(256) void gemm_mma(
    const float* __restrict__ A, const float* __restrict__ B,
    float* __restrict__ C, int M, int N, int K_)
{
    extern __shared__ float sm[];
    const uint32_t sb = smem_u32(sm);

    const int tid  = threadIdx.x;
    const int wid  = tid >> 5;
    const int lane = tid & 31;
    const int r8   = lane >> 2;
    const int c4   = lane & 3;
    const int wm   = (wid & 1) * 64;
    const int wn   = (wid >> 1) * 32;
    const int bm   = blockIdx.y * 128;
    const int bn   = blockIdx.x * 128;
    const int nk   = K_ >> 5;

    float acc[4][4][4];
    #pragma unroll
    for (int mt = 0; mt < 4; mt++)
        #pragma unroll
        for (int nt = 0; nt < 4; nt++)
            #pragma unroll
            for (int j = 0; j < 4; j++) acc[mt][nt][j] = 0.0f;

    auto issue = [&](int kc) {
        const int s = kc % GSTAGES;
        const uint32_t dA = sb + (uint32_t)(s * STAGE_F) * 4;
        const uint32_t dB = dA + 128 * GP * 4;
        const float* gA = A + (size_t)bm * K_ + kc * 32;
        const float* gB = B + (size_t)bn * K_ + kc * 32;
        #pragma unroll
        for (int i = 0; i < 4; i++) {
            const int idx = tid + 256 * i;
            const int row = idx >> 3, cg = idx & 7;
            cp16(dA + (row * GP + cg * 4) * 4, gA + (size_t)row * K_ + cg * 4);
            cp16(dB + (row * GP + cg * 4) * 4, gB + (size_t)row * K_ + cg * 4);
        }
        cp_commit();
    };

    issue(0);
    issue(1);

    for (int kc = 0; kc < nk; kc++) {
        cp_wait1();
        __syncthreads();

        const float* sA = sm + (kc % GSTAGES) * STAGE_F;
        const float* sB = sA + 128 * GP;

        #pragma unroll
        for (int ks = 0; ks < 4; ks++) {
            const int k0 = ks * 8;
            float af[4][4], bf[4][2];
            #pragma unroll
            for (int mt = 0; mt < 4; mt++) {
                const int row = wm + mt * 16 + r8;
                af[mt][0] = sA[row * GP + k0 + c4];
                af[mt][1] = sA[(row + 8) * GP + k0 + c4];
                af[mt][2] = sA[row * GP + k0 + c4 + 4];
                af[mt][3] = sA[(row + 8) * GP + k0 + c4 + 4];
            }
            #pragma unroll
            for (int nt = 0; nt < 4; nt++) {
                const int col = wn + nt * 8 + r8;
                bf[nt][0] = sB[col * GP + k0 + c4];
                bf[nt][1] = sB[col * GP + k0 + c4 + 4];
            }
            #pragma unroll
            for (int mt = 0; mt < 4; mt++)
                #pragma unroll
                for (int nt = 0; nt < 4; nt++)
                    mma_tf32(acc[mt][nt], af[mt], bf[nt]);
        }
        __syncthreads();
        if (kc + 2 < nk) issue(kc + 2);
    }

    #pragma unroll
    for (int mt = 0; mt < 4; mt++) {
        const int row = bm + wm + mt * 16 + r8;
        #pragma unroll
        for (int nt = 0; nt < 4; nt++) {
            const int col = bn + wn + nt * 8 + 2 * c4;
            *(float2*)&C[(size_t)row * N + col] =
                make_float2(acc[mt][nt][0], acc[mt][nt][1]);
            *(float2*)&C[(size_t)(row + 8) * N + col] =
                make_float2(acc[mt][nt][2], acc[mt][nt][3]);
        }
    }
}

// =====================================================================
// bf16x3 compensated NT GEMM — validated (V proj, out proj)
// =====================================================================
#define BP        20
#define BSTAGE_U  (4 * 128 * BP)
#define B3STAGES  3
#define B3_SMEM   (B3STAGES * BSTAGE_U * 4)

__global__ __launch_bounds__(256) void gemm_bf3(
    const __nv_bfloat16* __restrict__ Ah, const __nv_bfloat16* __restrict__ Al,
    const __nv_bfloat16* __restrict__ Bh, const __nv_bfloat16* __restrict__ Bl,
    float* __restrict__ C, int M, int N, int K_)
{
    extern __shared__ uint32_t smu[];
    const uint32_t sb = smem_u32(smu);

    const int tid  = threadIdx.x;
    const int wid  = tid >> 5;
    const int lane = tid & 31;
    const int r8   = lane >> 2;
    const int c4   = lane & 3;
    const int wm   = (wid & 1) * 64;
    const int wn   = (wid >> 1) * 32;
    const int bm   = blockIdx.y * 128;
    const int bn   = blockIdx.x * 128;
    const int nk   = K_ >> 5;

    float acc[4][4][4];
    #pragma unroll
    for (int mt = 0; mt < 4; mt++)
        #pragma unroll
        for (int nt = 0; nt < 4; nt++)
            #pragma unroll
            for (int j = 0; j < 4; j++) acc[mt][nt][j] = 0.0f;

    auto issue = [&](int kc) {
        const int s = kc % B3STAGES;
        const uint32_t base = sb + (uint32_t)(s * BSTAGE_U) * 4;
        const __nv_bfloat16* gsrc[4] = {
            Ah + (size_t)bm * K_ + kc * 32, Al + (size_t)bm * K_ + kc * 32,
            Bh + (size_t)bn * K_ + kc * 32, Bl + (size_t)bn * K_ + kc * 32 };
        #pragma unroll
        for (int i = 0; i < 8; i++) {
            const int idx = tid + 256 * i;
            const int arr = idx >> 9;
            const int rem = idx & 511;
            const int row = rem >> 2, cg = rem & 3;
            cp16(base + (uint32_t)(arr * 128 * BP + row * BP + cg * 4) * 4,
                 gsrc[arr] + (size_t)row * K_ + cg * 8);
        }
        cp_commit();
    };

    issue(0);
    issue(1);

    for (int kc = 0; kc < nk; kc++) {
        cp_wait1();
        __syncthreads();

        const uint32_t* sAh = smu + (kc % B3STAGES) * BSTAGE_U;
        const uint32_t* sAl = sAh + 128 * BP;
        const uint32_t* sBh = sAl + 128 * BP;
        const uint32_t* sBl = sBh + 128 * BP;

        #pragma unroll
        for (int ks = 0; ks < 2; ks++) {
            const int w0 = ks * 8;
            uint32_t ah[4][4], al[4][4], bh[4][2], bl[4][2];
            #pragma unroll
            for (int mt = 0; mt < 4; mt++) {
                const int row = wm + mt * 16 + r8;
                ah[mt][0] = sAh[row * BP + w0 + c4];
                ah[mt][1] = sAh[(row + 8) * BP + w0 + c4];
                ah[mt][2] = sAh[row * BP + w0 + c4 + 4];
                ah[mt][3] = sAh[(row + 8) * BP + w0 + c4 + 4];
                al[mt][0] = sAl[row * BP + w0 + c4];
                al[mt][1] = sAl[(row + 8) * BP + w0 + c4];
                al[mt][2] = sAl[row * BP + w0 + c4 + 4];
                al[mt][3] = sAl[(row + 8) * BP + w0 + c4 + 4];
            }
            #pragma unroll
            for (int nt = 0; nt < 4; nt++) {
                const int col = wn + nt * 8 + r8;
                bh[nt][0] = sBh[col * BP + w0 + c4];
                bh[nt][1] = sBh[col * BP + w0 + c4 + 4];
                bl[nt][0] = sBl[col * BP + w0 + c4];
                bl[nt][1] = sBl[col * BP + w0 + c4 + 4];
            }
            #pragma unroll
            for (int mt = 0; mt < 4; mt++)
                #pragma unroll
                for (int nt = 0; nt < 4; nt++) {
                    mma_bf16(acc[mt][nt], ah[mt], bh[nt]);
                    mma_bf16(acc[mt][nt], ah[mt], bl[nt]);
                    mma_bf16(acc[mt][nt], al[mt], bh[nt]);
                }
        }
        __syncthreads();
        if (kc + 2 < nk) issue(kc + 2);
    }

    #pragma unroll
    for (int mt = 0; mt < 4; mt++) {
        const int row = bm + wm + mt * 16 + r8;
        #pragma unroll
        for (int nt = 0; nt < 4; nt++) {
            const int col = bn + wn + nt * 8 + 2 * c4;
            *(float2*)&C[(size_t)row * N + col] =
                make_float2(acc[mt][nt][0], acc[mt][nt][1]);
            *(float2*)&C[(size_t)(row + 8) * N + col] =
                make_float2(acc[mt][nt][2], acc[mt][nt][3]);
        }
    }
}

// =====================================================================
// Flash attention v3:
//   S  = QK^T        : tf32 mma (softmax-attenuated path)
//   softmax          : fp32, per-row owner threads
//   O += P V         : bf16x3 compensated mma (pass-through path)
// O lives in mma C fragments; per-row corr/invl via smem arrays.
// =====================================================================
#define FP 68                       // float pitch (Qs/Ks/Ss)
#define HP 36                       // uint32 pitch for bf16 arrays (72 bf16)
#define FLASH_SMEM ((3 * 64 * FP + 4 * 64 * HP + 128) * 4)

__global__ __launch_bounds__(256) void flash_kernel()
{
    extern __shared__ float fsm[];
    float*    Qs  = fsm;
    float*    Ks  = Qs + 64 * FP;
    float*    Ss  = Ks + 64 * FP;
    uint32_t* Ph  = (uint32_t*)(Ss + 64 * FP);
    uint32_t* Pl  = Ph + 64 * HP;
    uint32_t* Vth = Pl + 64 * HP;
    uint32_t* Vtl = Vth + 64 * HP;
    float* corr_s = (float*)(Vtl + 64 * HP);
    float* invl_s = corr_s + 64;

    const int tid  = threadIdx.x;
    const int lane = tid & 31;
    const int wid  = tid >> 5;
    const int r8   = lane >> 2;
    const int c4   = lane & 3;
    const int wm   = (wid & 3) * 16;   // warp m-group
    const int wn   = (wid >> 2) * 32;  // warp n-half
    const int tx   = tid & 15;
    const int ty   = tid >> 4;
    const int r    = tid & 63;
    const int cg   = tid >> 6;
    const int bh   = blockIdx.y;
    const int b    = bh >> 4, h = bh & 15;
    const int q0   = blockIdx.x * 64;

    const float* Qh = g_Q + (size_t)bh * (SQ * HD);
    const float* Kh = g_K + (size_t)bh * (SKV * HD);
    const float* Vh = g_V + (size_t)bh * (SKV * HD);

    __nv_bfloat16* VthH = (__nv_bfloat16*)Vth;
    __nv_bfloat16* VtlH = (__nv_bfloat16*)Vtl;

    // Q -> Qs (tf32, scaled by 1/HD)
    const float qsc = 1.0f / (float)HD;
    #pragma unroll
    for (int it = 0; it < 4; it++) {
        int idx = tid + it * 256;
        int row = idx >> 4, cc = idx & 15;
        float4 q = *(const float4*)(Qh + (size_t)(q0 + row) * HD + cc * 4);
        *(float4*)&Qs[row * FP + cc * 4] = make_float4(
            rna_tf32(q.x * qsc), rna_tf32(q.y * qsc),
            rna_tf32(q.z * qsc), rna_tf32(q.w * qsc));
    }

    float m_i[4], l_i[4];
    float oacc[4][4];                  // PV C fragments: 4 n-tiles x 4 floats
    #pragma unroll
    for (int i = 0; i < 4; i++) {
        m_i[i] = -INFINITY; l_i[i] = 0.0f;
        #pragma unroll
        for (int j = 0; j < 4; j++) oacc[i][j] = 0.0f;
    }

    for (int kc = 0; kc < SKV / 64; kc++) {
        const int n0 = kc * 64;
        float4 kv[4], vv[4];
        #pragma unroll
        for (int it = 0; it < 4; it++) {
            int cc = cg + it * 4;
            kv[it] = *(const float4*)(Kh + (size_t)(n0 + r) * HD + cc * 4);
            vv[it] = *(const float4*)(Vh + (size_t)(n0 + r) * HD + cc * 4);
        }
        __syncthreads();   // prev chunk: PV reads of Ph/Pl/Vt*, S reads of Ks done
        #pragma unroll
        for (int it = 0; it < 4; it++) {
            int cc = cg + it * 4;
            *(float4*)&Ks[r * FP + cc * 4] = make_float4(
                rna_tf32(kv[it].x), rna_tf32(kv[it].y),
                rna_tf32(kv[it].z), rna_tf32(kv[it].w));
            // V transpose + hi/lo split: Vt[d][kv]
            float vals[4] = {vv[it].x, vv[it].y, vv[it].z, vv[it].w};
            #pragma unroll
            for (int j = 0; j < 4; j++) {
                int d = cc * 4 + j;
                float v = vals[j];
                __nv_bfloat16 hv = __float2bfloat16_rn(v);
                __nv_bfloat16 lv = __float2bfloat16_rn(v - __bfloat162float(hv));
                VthH[d * (2 * HP) + r] = hv;
                VtlH[d * (2 * HP) + r] = lv;
            }
        }
        __syncthreads();

        // ---- S = Q K^T (tf32 mma), warp tile m16 x n32 ----
        float sf[4][4] = {};
        #pragma unroll
        for (int ks = 0; ks < 8; ks++) {
            const int k0 = ks * 8;
            float af[4];
            af[0] = Qs[(wm + r8) * FP + k0 + c4];
            af[1] = Qs[(wm + r8 + 8) * FP + k0 + c4];
            af[2] = Qs[(wm + r8) * FP + k0 + c4 + 4];
            af[3] = Qs[(wm + r8 + 8) * FP + k0 + c4 + 4];
            #pragma unroll
            for (int nt = 0; nt < 4; nt++) {
                float bf[2];
                bf[0] = Ks[(wn + nt * 8 + r8) * FP + k0 + c4];
                bf[1] = Ks[(wn + nt * 8 + r8) * FP + k0 + c4 + 4];
                mma_tf32(sf[nt], af, bf);
            }
        }
        #pragma unroll
        for (int nt = 0; nt < 4; nt++) {
            const int col = wn + nt * 8 + 2 * c4;
            *(float2*)&Ss[(wm + r8) * FP + col]     = make_float2(sf[nt][0], sf[nt][1]);
            *(float2*)&Ss[(wm + r8 + 8) * FP + col] = make_float2(sf[nt][2], sf[nt][3]);
        }
        __syncthreads();

        // ---- online softmax: thread owns rows ty*4..+3, cols tx*4..+3 ----
        #pragma unroll
        for (int ri = 0; ri < 4; ri++) {
            const int row = ty * 4 + ri;
            float4 sv = *(const float4*)&Ss[row * FP + tx * 4];
            float s0 = sv.x, s1 = sv.y, s2 = sv.z, s3 = sv.w;
            float mx = fmaxf(fmaxf(s0, s1), fmaxf(s2, s3));
            #pragma unroll
            for (int off = 1; off < 16; off <<= 1)
                mx = fmaxf(mx, __shfl_xor_sync(0xffffffffu, mx, off));
            float mnew = fmaxf(m_i[ri], mx);
            float corrv = __expf(m_i[ri] - mnew);
            s0 = __expf(s0 - mnew); s1 = __expf(s1 - mnew);
            s2 = __expf(s2 - mnew); s3 = __expf(s3 - mnew);
            float sum = s0 + s1 + s2 + s3;
            #pragma unroll
            for (int off = 1; off < 16; off <<= 1)
                sum += __shfl_xor_sync(0xffffffffu, sum, off);
            l_i[ri] = l_i[ri] * corrv + sum;
            m_i[ri] = mnew;
            // P -> bf16 hi/lo pairs (A-fragment layout)
            __nv_bfloat16 h0 = __float2bfloat16_rn(s0), h1 = __float2bfloat16_rn(s1);
            __nv_bfloat16 h2 = __float2bfloat16_rn(s2), h3 = __float2bfloat16_rn(s3);
            __nv_bfloat16 e0 = __float2bfloat16_rn(s0 - __bfloat162float(h0));
            __nv_bfloat16 e1 = __float2bfloat16_rn(s1 - __bfloat162float(h1));
            __nv_bfloat16 e2 = __float2bfloat16_rn(s2 - __bfloat162float(h2));
            __nv_bfloat16 e3 = __float2bfloat16_rn(s3 - __bfloat162float(h3));
            Ph[row * HP + tx * 2]     = pack_bf16(h0, h1);
            Ph[row * HP + tx * 2 + 1] = pack_bf16(h2, h3);
            Pl[row * HP + tx * 2]     = pack_bf16(e0, e1);
            Pl[row * HP + tx * 2 + 1] = pack_bf16(e2, e3);
            if (tx == 0) corr_s[row] = corrv;
        }
        __syncthreads();

        // ---- rescale O fragments, then O += P V (bf16x3 mma) ----
        {
            float cA = corr_s[wm + r8];
            float cB = corr_s[wm + 8 + r8];
            #pragma unroll
            for (int nt = 0; nt < 4; nt++) {
                oacc[nt][0] *= cA; oacc[nt][1] *= cA;
                oacc[nt][2] *= cB; oacc[nt][3] *= cB;
            }
        }
        #pragma unroll
        for (int ks = 0; ks < 4; ks++) {
            const int w0 = ks * 8;
            uint32_t ah[4], al[4];
            ah[0] = Ph[(wm + r8) * HP + w0 + c4];
            ah[1] = Ph[(wm + 8 + r8) * HP + w0 + c4];
            ah[2] = Ph[(wm + r8) * HP + w0 + 4 + c4];
            ah[3] = Ph[(wm + 8 + r8) * HP + w0 + 4 + c4];
            al[0] = Pl[(wm + r8) * HP + w0 + c4];
            al[1] = Pl[(wm + 8 + r8) * HP + w0 + c4];
            al[2] = Pl[(wm + r8) * HP + w0 + 4 + c4];
            al[3] = Pl[(wm + 8 + r8) * HP + w0 + 4 + c4];
            #pragma unroll
            for (int nt = 0; nt < 4; nt++) {
                const int col = wn + nt * 8 + r8;
                uint32_t bhf[2], blf[2];
                bhf[0] = Vth[col * HP + w0 + c4];
                bhf[1] = Vth[col * HP + w0 + 4 + c4];
                blf[0] = Vtl[col * HP + w0 + c4];
                blf[1] = Vtl[col * HP + w0 + 4 + c4];
                mma_bf16(oacc[nt], ah, bhf);
                mma_bf16(oacc[nt], ah, blf);
                mma_bf16(oacc[nt], al, bhf);
            }
        }
    }

    // per-row 1/l
    if (tx == 0) {
        #pragma unroll
        for (int ri = 0; ri < 4; ri++)
            invl_s[ty * 4 + ri] = 1.0f / l_i[ri];
    }
    __syncthreads();

    // epilogue from fragments: AO[b, q0+row, h*64 + col]
    {
        float iA = invl_s[wm + r8];
        float iB = invl_s[wm + 8 + r8];
        float* AOp = g_AO + (size_t)b * (SQ * DQ_) + h * HD;
        #pragma unroll
        for (int nt = 0; nt < 4; nt++) {
            const int col = wn + nt * 8 + 2 * c4;
            const int row0 = q0 + wm + r8;
            *(float2*)&AOp[(size_t)row0 * DQ_ + col] =
                make_float2(oacc[nt][0] * iA, oacc[nt][1] * iA);
            *(float2*)&AOp[(size_t)(row0 + 8) * DQ_ + col] =
                make_float2(oacc[nt][2] * iB, oacc[nt][3] * iB);
        }
    }
}

// =====================================================================
// launch
// =====================================================================
static inline void launch_round(const float* in, float* out, int n) {
    int n4 = n / 4;
    round_kernel<<<(n4 + 255) / 256, 256>>>((const float4*)in, (float4*)out, n4);
}
static inline void launch_split(const float* in, __nv_bfloat16* hi, __nv_bfloat16* lo, int n) {
    int n2 = n / 2;
    split_kernel<<<(n2 + 255) / 256, 256>>>((const float2*)in,
        (__nv_bfloat162*)hi, (__nv_bfloat162*)lo, n2);
}

extern "C" void kernel_launch(void* const* d_in, const int* in_sizes, int n_in,
                              void* d_out, int out_size)
{
    (void)in_sizes; (void)n_in; (void)out_size;
    const float* x_q  = (const float*)d_in[0];
    const float* x_kv = (const float*)d_in[1];
    const float* Wq   = (const float*)d_in[2];
    const float* Wk   = (const float*)d_in[3];
    const float* Wv   = (const float*)d_in[4];
    const float* Wo   = (const float*)d_in[5];
    float* out = (float*)d_out;

    float *Q, *K, *V, *AO, *xq, *xkv, *wq, *wk;
    __nv_bfloat16 *xkvh, *xkvl, *wvh, *wvl, *aoh, *aol, *woh, *wol;
    cudaGetSymbolAddress((void**)&Q,    g_Q);
    cudaGetSymbolAddress((void**)&K,    g_K);
    cudaGetSymbolAddress((void**)&V,    g_V);
    cudaGetSymbolAddress((void**)&AO,   g_AO);
    cudaGetSymbolAddress((void**)&xq,   g_xq);
    cudaGetSymbolAddress((void**)&xkv,  g_xkv);
    cudaGetSymbolAddress((void**)&wq,   g_wq);
    cudaGetSymbolAddress((void**)&wk,   g_wk);
    cudaGetSymbolAddress((void**)&xkvh, g_xkv_h);
    cudaGetSymbolAddress((void**)&xkvl, g_xkv_l);
    cudaGetSymbolAddress((void**)&wvh,  g_wv_h);
    cudaGetSymbolAddress((void**)&wvl,  g_wv_l);
    cudaGetSymbolAddress((void**)&aoh,  g_ao_h);
    cudaGetSymbolAddress((void**)&aol,  g_ao_l);
    cudaGetSymbolAddress((void**)&woh,  g_wo_h);
    cudaGetSymbolAddress((void**)&wol,  g_wo_l);

    cudaFuncSetAttribute(gemm_mma, cudaFuncAttributeMaxDynamicSharedMemorySize, GEMM_SMEM);
    cudaFuncSetAttribute(gemm_bf3, cudaFuncAttributeMaxDynamicSharedMemorySize, B3_SMEM);
    cudaFuncSetAttribute(flash_kernel, cudaFuncAttributeMaxDynamicSharedMemorySize, FLASH_SMEM);

    // prepasses
    launch_round(x_q,  xq,  BB * SQ * DQ_);
    launch_round(x_kv, xkv, BB * SKV * DKV_);
    launch_round(Wq, wq, DQ_ * DQ_);
    launch_round(Wk, wk, DQ_ * DKV_);
    launch_split(x_kv, xkvh, xkvl, BB * SKV * DKV_);
    launch_split(Wv,   wvh,  wvl,  DQ_ * DKV_);
    launch_split(Wo,   woh,  wol,  DQ_ * DQ_);

    // Q = x_q @ Wq^T  (tf32 — softmax-attenuated path)
    gemm_mma<<<dim3(DQ_ / 128, (BB * SQ) / 128),  256, GEMM_SMEM>>>(xq,  wq, Q, BB * SQ,  DQ_, DQ_);
    // K = x_kv @ Wk^T (tf32)
    gemm_mma<<<dim3(DQ_ / 128, (BB * SKV) / 128), 256, GEMM_SMEM>>>(xkv, wk, K, BB * SKV, DQ_, DKV_);
    // V = x_kv @ Wv^T (bf16x3)
    gemm_bf3<<<dim3(DQ_ / 128, (BB * SKV) / 128), 256, B3_SMEM>>>(
        xkvh, xkvl, wvh, wvl, V, BB * SKV, DQ_, DKV_);
    // attention (S tf32 mma, softmax fp32, PV bf16x3 mma)
    flash_kernel<<<dim3(SQ / 64, BB * NH), 256, FLASH_SMEM>>>();
    // split AO, then out = AO @ Wo^T (bf16x3)
    launch_split(AO, aoh, aol, BB * SQ * DQ_);
    gemm_bf3<<<dim3(DQ_ / 128, (BB * SQ) / 128), 256, B3_SMEM>>>(
        aoh, aol, woh, wol, out, BB * SQ, DQ_, DQ_);
}

// round 8
// speedup vs baseline: 2.7304x; 1.4198x over previous
#include <cuda_runtime.h>
#include <cuda_bf16.h>
#include <math.h>
#include <cstdint>

// ---------------- problem constants ----------------
#define BB   2
#define SQ   1024
#define SKV  4096
#define DQ_  1024
#define DKV_ 768
#define NH   16
#define HD   64

// ---------------- scratch ----------------
__device__ float g_Q [BB * SQ  * DQ_];
__device__ float g_K [BB * SKV * DQ_];
__device__ float g_V [BB * SKV * DQ_];
__device__ float g_AO[BB * SQ  * DQ_];
// tf32-rounded operand copies (Q/K projection path)
__device__ float g_xq [BB * SQ  * DQ_];
__device__ float g_xkv[BB * SKV * DKV_];
__device__ float g_wq [DQ_ * DQ_];
__device__ float g_wk [DQ_ * DKV_];
// bf16 hi/lo splits (V projection + output projection paths)
__device__ __align__(256) __nv_bfloat16 g_xkv_h[BB * SKV * DKV_];
__device__ __align__(256) __nv_bfloat16 g_xkv_l[BB * SKV * DKV_];
__device__ __align__(256) __nv_bfloat16 g_wv_h [DQ_ * DKV_];
__device__ __align__(256) __nv_bfloat16 g_wv_l [DQ_ * DKV_];
__device__ __align__(256) __nv_bfloat16 g_ao_h [BB * SQ * DQ_];
__device__ __align__(256) __nv_bfloat16 g_ao_l [BB * SQ * DQ_];
__device__ __align__(256) __nv_bfloat16 g_wo_h [DQ_ * DQ_];
__device__ __align__(256) __nv_bfloat16 g_wo_l [DQ_ * DQ_];

// =====================================================================
// helpers
// =====================================================================
__device__ __forceinline__ uint32_t smem_u32(const void* p) {
    uint32_t a;
    asm("{ .reg .u64 t; cvta.to.shared.u64 t, %1; cvt.u32.u64 %0, t; }" : "=r"(a) : "l"(p));
    return a;
}
__device__ __forceinline__ float rna_tf32(float x) {
    uint32_t r;
    asm("cvt.rna.tf32.f32 %0, %1;" : "=r"(r) : "f"(x));
    return __uint_as_float(r);
}
__device__ __forceinline__ void cp16(uint32_t dst, const void* src) {
    asm volatile("cp.async.cg.shared.global [%0], [%1], 16;" :: "r"(dst), "l"(src) : "memory");
}
__device__ __forceinline__ void cp_commit() {
    asm volatile("cp.async.commit_group;" ::: "memory");
}
__device__ __forceinline__ void cp_wait1() {
    asm volatile("cp.async.wait_group 1;" ::: "memory");
}
__device__ __forceinline__ uint32_t pack_bf16(__nv_bfloat16 a, __nv_bfloat16 b) {
    __nv_bfloat162 t{a, b};
    return *(uint32_t*)&t;
}
// pack two floats to bf16x2 (hi part)
__device__ __forceinline__ uint32_t pack_hi(float x, float y) {
    return pack_bf16(__float2bfloat16_rn(x), __float2bfloat16_rn(y));
}
// pack residuals
__device__ __forceinline__ uint32_t pack_lo(float x, float y) {
    __nv_bfloat16 hx = __float2bfloat16_rn(x);
    __nv_bfloat16 hy = __float2bfloat16_rn(y);
    return pack_bf16(__float2bfloat16_rn(x - __bfloat162float(hx)),
                     __float2bfloat16_rn(y - __bfloat162float(hy)));
}

// tf32 m16n8k8: D += A * B^T
__device__ __forceinline__ void mma_tf32(float* d, const float* a, const float* b) {
    asm volatile(
        "mma.sync.aligned.m16n8k8.row.col.f32.tf32.tf32.f32 "
        "{%0,%1,%2,%3}, {%4,%5,%6,%7}, {%8,%9}, {%0,%1,%2,%3};"
        : "+f"(d[0]), "+f"(d[1]), "+f"(d[2]), "+f"(d[3])
        : "r"(__float_as_uint(a[0])), "r"(__float_as_uint(a[1])),
          "r"(__float_as_uint(a[2])), "r"(__float_as_uint(a[3])),
          "r"(__float_as_uint(b[0])), "r"(__float_as_uint(b[1])));
}

// bf16 m16n8k16: D += A * B^T
__device__ __forceinline__ void mma_bf16(float* d, const uint32_t* a, const uint32_t* b) {
    asm volatile(
        "mma.sync.aligned.m16n8k16.row.col.f32.bf16.bf16.f32 "
        "{%0,%1,%2,%3}, {%4,%5,%6,%7}, {%8,%9}, {%0,%1,%2,%3};"
        : "+f"(d[0]), "+f"(d[1]), "+f"(d[2]), "+f"(d[3])
        : "r"(a[0]), "r"(a[1]), "r"(a[2]), "r"(a[3]),
          "r"(b[0]), "r"(b[1]));
}

// =====================================================================
// prepass kernels
// =====================================================================
__global__ void round_kernel(const float4* __restrict__ in, float4* __restrict__ out, int n4) {
    int i = blockIdx.x * blockDim.x + threadIdx.x;
    if (i < n4) {
        float4 v = in[i];
        v.x = rna_tf32(v.x); v.y = rna_tf32(v.y);
        v.z = rna_tf32(v.z); v.w = rna_tf32(v.w);
        out[i] = v;
    }
}

__global__ void split_kernel(const float2* __restrict__ in,
                             __nv_bfloat162* __restrict__ hi,
                             __nv_bfloat162* __restrict__ lo, int n2) {
    int i = blockIdx.x * blockDim.x + threadIdx.x;
    if (i < n2) {
        float2 v = in[i];
        __nv_bfloat16 hx = __float2bfloat16_rn(v.x);
        __nv_bfloat16 hy = __float2bfloat16_rn(v.y);
        __nv_bfloat16 lx = __float2bfloat16_rn(v.x - __bfloat162float(hx));
        __nv_bfloat16 ly = __float2bfloat16_rn(v.y - __bfloat162float(hy));
        hi[i] = __nv_bfloat162{hx, hy};
        lo[i] = __nv_bfloat162{lx, ly};
    }
}

// =====================================================================
// tf32 mma.sync NT GEMM (Q/K projections) — validated
// =====================================================================
#define GP        36
#define STAGE_F   (2 * 128 * GP)
#define GSTAGES   3
#define GEMM_SMEM (GSTAGES * STAGE_F * 4)

__global__ __launch_bounds__(256) void gemm_mma(
    const float* __restrict__ A, const float* __restrict__ B,
    float* __restrict__ C, int M, int N, int K_)
{
    extern __shared__ float sm[];
    const uint32_t sb = smem_u32(sm);

    const int tid  = threadIdx.x;
    const int wid  = tid >> 5;
    const int lane = tid & 31;
    const int r8   = lane >> 2;
    const int c4   = lane & 3;
    const int wm   = (wid & 1) * 64;
    const int wn   = (wid >> 1) * 32;
    const int bm   = blockIdx.y * 128;
    const int bn   = blockIdx.x * 128;
    const int nk   = K_ >> 5;

    float acc[4][4][4];
    #pragma unroll
    for (int mt = 0; mt < 4; mt++)
        #pragma unroll
        for (int nt = 0; nt < 4; nt++)
            #pragma unroll
            for (int j = 0; j < 4; j++) acc[mt][nt][j] = 0.0f;

    auto issue = [&](int kc) {
        const int s = kc % GSTAGES;
        const uint32_t dA = sb + (uint32_t)(s * STAGE_F) * 4;
        const uint32_t dB = dA + 128 * GP * 4;
        const float* gA = A + (size_t)bm * K_ + kc * 32;
        const float* gB = B + (size_t)bn * K_ + kc * 32;
        #pragma unroll
        for (int i = 0; i < 4; i++) {
            const int idx = tid + 256 * i;
            const int row = idx >> 3, cg = idx & 7;
            cp16(dA + (row * GP + cg * 4) * 4, gA + (size_t)row * K_ + cg * 4);
            cp16(dB + (row * GP + cg * 4) * 4, gB + (size_t)row * K_ + cg * 4);
        }
        cp_commit();
    };

    issue(0);
    issue(1);

    for (int kc = 0; kc < nk; kc++) {
        cp_wait1();
        __syncthreads();

        const float* sA = sm + (kc % GSTAGES) * STAGE_F;
        const float* sB = sA + 128 * GP;

        #pragma unroll
        for (int ks = 0; ks < 4; ks++) {
            const int k0 = ks * 8;
            float af[4][4], bf[4][2];
            #pragma unroll
            for (int mt = 0; mt < 4; mt++) {
                const int row = wm + mt * 16 + r8;
                af[mt][0] = sA[row * GP + k0 + c4];
                af[mt][1] = sA[(row + 8) * GP + k0 + c4];
                af[mt][2] = sA[row * GP + k0 + c4 + 4];
                af[mt][3] = sA[(row + 8) * GP + k0 + c4 + 4];
            }
            #pragma unroll
            for (int nt = 0; nt < 4; nt++) {
                const int col = wn + nt * 8 + r8;
                bf[nt][0] = sB[col * GP + k0 + c4];
                bf[nt][1] = sB[col * GP + k0 + c4 + 4];
            }
            #pragma unroll
            for (int mt = 0; mt < 4; mt++)
                #pragma unroll
                for (int nt = 0; nt < 4; nt++)
                    mma_tf32(acc[mt][nt], af[mt], bf[nt]);
        }
        __syncthreads();
        if (kc + 2 < nk) issue(kc + 2);
    }

    #pragma unroll
    for (int mt = 0; mt < 4; mt++) {
        const int row = bm + wm + mt * 16 + r8;
        #pragma unroll
        for (int nt = 0; nt < 4; nt++) {
            const int col = bn + wn + nt * 8 + 2 * c4;
            *(float2*)&C[(size_t)row * N + col] =
                make_float2(acc[mt][nt][0], acc[mt][nt][1]);
            *(float2*)&C[(size_t)(row + 8) * N + col] =
                make_float2(acc[mt][nt][2], acc[mt][nt][3]);
        }
    }
}

// =====================================================================
// bf16x3 compensated NT GEMM — validated (V proj, out proj)
// =====================================================================
#define BP        20
#define BSTAGE_U  (4 * 128 * BP)
#define B3STAGES  3
#define B3_SMEM   (B3STAGES * BSTAGE_U * 4)

__global__ __launch_bounds__(256) void gemm_bf3(
    const __nv_bfloat16* __restrict__ Ah, const __nv_bfloat16* __restrict__ Al,
    const __nv_bfloat16* __restrict__ Bh, const __nv_bfloat16* __restrict__ Bl,
    float* __restrict__ C, int M, int N, int K_)
{
    extern __shared__ uint32_t smu[];
    const uint32_t sb = smem_u32(smu);

    const int tid  = threadIdx.x;
    const int wid  = tid >> 5;
    const int lane = tid & 31;
    const int r8   = lane >> 2;
    const int c4   = lane & 3;
    const int wm   = (wid & 1) * 64;
    const int wn   = (wid >> 1) * 32;
    const int bm   = blockIdx.y * 128;
    const int bn   = blockIdx.x * 128;
    const int nk   = K_ >> 5;

    float acc[4][4][4];
    #pragma unroll
    for (int mt = 0; mt < 4; mt++)
        #pragma unroll
        for (int nt = 0; nt < 4; nt++)
            #pragma unroll
            for (int j = 0; j < 4; j++) acc[mt][nt][j] = 0.0f;

    auto issue = [&](int kc) {
        const int s = kc % B3STAGES;
        const uint32_t base = sb + (uint32_t)(s * BSTAGE_U) * 4;
        const __nv_bfloat16* gsrc[4] = {
            Ah + (size_t)bm * K_ + kc * 32, Al + (size_t)bm * K_ + kc * 32,
            Bh + (size_t)bn * K_ + kc * 32, Bl + (size_t)bn * K_ + kc * 32 };
        #pragma unroll
        for (int i = 0; i < 8; i++) {
            const int idx = tid + 256 * i;
            const int arr = idx >> 9;
            const int rem = idx & 511;
            const int row = rem >> 2, cg = rem & 3;
            cp16(base + (uint32_t)(arr * 128 * BP + row * BP + cg * 4) * 4,
                 gsrc[arr] + (size_t)row * K_ + cg * 8);
        }
        cp_commit();
    };

    issue(0);
    issue(1);

    for (int kc = 0; kc < nk; kc++) {
        cp_wait1();
        __syncthreads();

        const uint32_t* sAh = smu + (kc % B3STAGES) * BSTAGE_U;
        const uint32_t* sAl = sAh + 128 * BP;
        const uint32_t* sBh = sAl + 128 * BP;
        const uint32_t* sBl = sBh + 128 * BP;

        #pragma unroll
        for (int ks = 0; ks < 2; ks++) {
            const int w0 = ks * 8;
            uint32_t ah[4][4], al[4][4], bh[4][2], bl[4][2];
            #pragma unroll
            for (int mt = 0; mt < 4; mt++) {
                const int row = wm + mt * 16 + r8;
                ah[mt][0] = sAh[row * BP + w0 + c4];
                ah[mt][1] = sAh[(row + 8) * BP + w0 + c4];
                ah[mt][2] = sAh[row * BP + w0 + c4 + 4];
                ah[mt][3] = sAh[(row + 8) * BP + w0 + c4 + 4];
                al[mt][0] = sAl[row * BP + w0 + c4];
                al[mt][1] = sAl[(row + 8) * BP + w0 + c4];
                al[mt][2] = sAl[row * BP + w0 + c4 + 4];
                al[mt][3] = sAl[(row + 8) * BP + w0 + c4 + 4];
            }
            #pragma unroll
            for (int nt = 0; nt < 4; nt++) {
                const int col = wn + nt * 8 + r8;
                bh[nt][0] = sBh[col * BP + w0 + c4];
                bh[nt][1] = sBh[col * BP + w0 + c4 + 4];
                bl[nt][0] = sBl[col * BP + w0 + c4];
                bl[nt][1] = sBl[col * BP + w0 + c4 + 4];
            }
            #pragma unroll
            for (int mt = 0; mt < 4; mt++)
                #pragma unroll
                for (int nt = 0; nt < 4; nt++) {
                    mma_bf16(acc[mt][nt], ah[mt], bh[nt]);
                    mma_bf16(acc[mt][nt], ah[mt], bl[nt]);
                    mma_bf16(acc[mt][nt], al[mt], bh[nt]);
                }
        }
        __syncthreads();
        if (kc + 2 < nk) issue(kc + 2);
    }

    #pragma unroll
    for (int mt = 0; mt < 4; mt++) {
        const int row = bm + wm + mt * 16 + r8;
        #pragma unroll
        for (int nt = 0; nt < 4; nt++) {
            const int col = bn + wn + nt * 8 + 2 * c4;
            *(float2*)&C[(size_t)row * N + col] =
                make_float2(acc[mt][nt][0], acc[mt][nt][1]);
            *(float2*)&C[(size_t)(row + 8) * N + col] =
                make_float2(acc[mt][nt][2], acc[mt][nt][3]);
        }
    }
}

// =====================================================================
// Flash attention v4 (FA2-style, register-resident P):
//   CTA = 128 queries; warp tile m16 x n64 (warp owns full score rows)
//   S  : tf32 mma -> C fragments stay in registers
//   softmax: in-register, shfl.xor over c4 group only
//   P  : repacked from S fragments directly into bf16 hi/lo A-fragments
//   PV : bf16x3 mma, O stays in C fragments across all chunks
// smem: Qs[128][68]f, Ks[64][68]f, Vth/Vtl[64][36]u32  (~71 KB)
// =====================================================================
#define FP 68
#define HP 36
#define FLASH_SMEM ((128 * FP + 64 * FP + 2 * 64 * HP) * 4)

__global__ __launch_bounds__(256, 2) void flash_kernel()
{
    extern __shared__ float fsm[];
    float*    Qs  = fsm;                        // [128][FP]
    float*    Ks  = Qs + 128 * FP;              // [64][FP]
    uint32_t* Vth = (uint32_t*)(Ks + 64 * FP);  // [64 d][HP]  (kv pairs)
    uint32_t* Vtl = Vth + 64 * HP;

    const int tid  = threadIdx.x;
    const int lane = tid & 31;
    const int wid  = tid >> 5;
    const int r8   = lane >> 2;
    const int c4   = lane & 3;
    const int wm   = wid * 16;      // warp rows wm..wm+15
    const int r    = tid & 63;
    const int cg   = tid >> 6;
    const int bh   = blockIdx.y;
    const int b    = bh >> 4, h = bh & 15;
    const int q0   = blockIdx.x * 128;

    const float* Qh = g_Q + (size_t)bh * (SQ * HD);
    const float* Kh = g_K + (size_t)bh * (SKV * HD);
    const float* Vh = g_V + (size_t)bh * (SKV * HD);

    __nv_bfloat16* VthH = (__nv_bfloat16*)Vth;
    __nv_bfloat16* VtlH = (__nv_bfloat16*)Vtl;

    // Q tile (128 rows) -> Qs, tf32-rounded, scaled by 1/HD
    const float qsc = 1.0f / (float)HD;
    #pragma unroll
    for (int it = 0; it < 8; it++) {
        int idx = tid + it * 256;           // 0..2047
        int row = idx >> 4, cc = idx & 15;
        float4 q = *(const float4*)(Qh + (size_t)(q0 + row) * HD + cc * 4);
        *(float4*)&Qs[row * FP + cc * 4] = make_float4(
            rna_tf32(q.x * qsc), rna_tf32(q.y * qsc),
            rna_tf32(q.z * qsc), rna_tf32(q.w * qsc));
    }

    float m0 = -INFINITY, m1 = -INFINITY, l0 = 0.0f, l1 = 0.0f;
    float oacc[8][4];
    #pragma unroll
    for (int dt = 0; dt < 8; dt++)
        #pragma unroll
        for (int j = 0; j < 4; j++) oacc[dt][j] = 0.0f;

    for (int kc = 0; kc < SKV / 64; kc++) {
        const int n0 = kc * 64;
        float4 kv[4], vv[4];
        #pragma unroll
        for (int it = 0; it < 4; it++) {
            int cc = cg + it * 4;
            kv[it] = *(const float4*)(Kh + (size_t)(n0 + r) * HD + cc * 4);
            vv[it] = *(const float4*)(Vh + (size_t)(n0 + r) * HD + cc * 4);
        }
        __syncthreads();   // prev chunk's mma reads of Ks/Vt done
        #pragma unroll
        for (int it = 0; it < 4; it++) {
            int cc = cg + it * 4;
            *(float4*)&Ks[r * FP + cc * 4] = make_float4(
                rna_tf32(kv[it].x), rna_tf32(kv[it].y),
                rna_tf32(kv[it].z), rna_tf32(kv[it].w));
            float vals[4] = {vv[it].x, vv[it].y, vv[it].z, vv[it].w};
            #pragma unroll
            for (int j = 0; j < 4; j++) {
                int d = cc * 4 + j;
                float v = vals[j];
                __nv_bfloat16 hv = __float2bfloat16_rn(v);
                __nv_bfloat16 lv = __float2bfloat16_rn(v - __bfloat162float(hv));
                VthH[d * (2 * HP) + r] = hv;
                VtlH[d * (2 * HP) + r] = lv;
            }
        }
        __syncthreads();

        // ---- S = Q K^T : warp tile m16 x n64 (8 n8-tiles) ----
        float sf[8][4];
        #pragma unroll
        for (int nt = 0; nt < 8; nt++)
            #pragma unroll
            for (int j = 0; j < 4; j++) sf[nt][j] = 0.0f;
        #pragma unroll
        for (int ks = 0; ks < 8; ks++) {
            const int k0 = ks * 8;
            float af[4];
            af[0] = Qs[(wm + r8) * FP + k0 + c4];
            af[1] = Qs[(wm + 8 + r8) * FP + k0 + c4];
            af[2] = Qs[(wm + r8) * FP + k0 + c4 + 4];
            af[3] = Qs[(wm + 8 + r8) * FP + k0 + c4 + 4];
            #pragma unroll
            for (int nt = 0; nt < 8; nt++) {
                float bf[2];
                bf[0] = Ks[(nt * 8 + r8) * FP + k0 + c4];
                bf[1] = Ks[(nt * 8 + r8) * FP + k0 + c4 + 4];
                mma_tf32(sf[nt], af, bf);
            }
        }

        // ---- in-register online softmax (rows rA=wm+r8, rB=wm+8+r8) ----
        float mxA = -INFINITY, mxB = -INFINITY;
        #pragma unroll
        for (int nt = 0; nt < 8; nt++) {
            mxA = fmaxf(mxA, fmaxf(sf[nt][0], sf[nt][1]));
            mxB = fmaxf(mxB, fmaxf(sf[nt][2], sf[nt][3]));
        }
        mxA = fmaxf(mxA, __shfl_xor_sync(0xffffffffu, mxA, 1));
        mxA = fmaxf(mxA, __shfl_xor_sync(0xffffffffu, mxA, 2));
        mxB = fmaxf(mxB, __shfl_xor_sync(0xffffffffu, mxB, 1));
        mxB = fmaxf(mxB, __shfl_xor_sync(0xffffffffu, mxB, 2));
        float mnA = fmaxf(m0, mxA), mnB = fmaxf(m1, mxB);
        float cA = __expf(m0 - mnA), cB = __expf(m1 - mnB);
        float sA = 0.0f, sB = 0.0f;
        #pragma unroll
        for (int nt = 0; nt < 8; nt++) {
            sf[nt][0] = __expf(sf[nt][0] - mnA);
            sf[nt][1] = __expf(sf[nt][1] - mnA);
            sf[nt][2] = __expf(sf[nt][2] - mnB);
            sf[nt][3] = __expf(sf[nt][3] - mnB);
            sA += sf[nt][0] + sf[nt][1];
            sB += sf[nt][2] + sf[nt][3];
        }
        sA += __shfl_xor_sync(0xffffffffu, sA, 1);
        sA += __shfl_xor_sync(0xffffffffu, sA, 2);
        sB += __shfl_xor_sync(0xffffffffu, sB, 1);
        sB += __shfl_xor_sync(0xffffffffu, sB, 2);
        l0 = l0 * cA + sA;  l1 = l1 * cB + sB;
        m0 = mnA;           m1 = mnB;
        #pragma unroll
        for (int dt = 0; dt < 8; dt++) {
            oacc[dt][0] *= cA; oacc[dt][1] *= cA;
            oacc[dt][2] *= cB; oacc[dt][3] *= cB;
        }

        // ---- O += P V : P A-fragments straight from S C-fragments ----
        #pragma unroll
        for (int kg = 0; kg < 4; kg++) {
            const float* f0 = sf[2 * kg];
            const float* f1 = sf[2 * kg + 1];
            uint32_t ah[4], al[4];
            ah[0] = pack_hi(f0[0], f0[1]);  al[0] = pack_lo(f0[0], f0[1]);
            ah[1] = pack_hi(f0[2], f0[3]);  al[1] = pack_lo(f0[2], f0[3]);
            ah[2] = pack_hi(f1[0], f1[1]);  al[2] = pack_lo(f1[0], f1[1]);
            ah[3] = pack_hi(f1[2], f1[3]);  al[3] = pack_lo(f1[2], f1[3]);
            const int w0 = kg * 8;
            #pragma unroll
            for (int dt = 0; dt < 8; dt++) {
                const int col = dt * 8 + r8;
                uint32_t bhf[2], blf[2];
                bhf[0] = Vth[col * HP + w0 + c4];
                bhf[1] = Vth[col * HP + w0 + 4 + c4];
                blf[0] = Vtl[col * HP + w0 + c4];
                blf[1] = Vtl[col * HP + w0 + 4 + c4];
                mma_bf16(oacc[dt], ah, bhf);
                mma_bf16(oacc[dt], ah, blf);
                mma_bf16(oacc[dt], al, bhf);
            }
        }
    }

    // epilogue: AO[b, q0+row, h*64 + col], normalize by 1/l
    {
        float iA = 1.0f / l0, iB = 1.0f / l1;
        float* AOp = g_AO + (size_t)b * (SQ * DQ_) + h * HD;
        const int row0 = q0 + wm + r8;
        #pragma unroll
        for (int dt = 0; dt < 8; dt++) {
            const int col = dt * 8 + 2 * c4;
            *(float2*)&AOp[(size_t)row0 * DQ_ + col] =
                make_float2(oacc[dt][0] * iA, oacc[dt][1] * iA);
            *(float2*)&AOp[(size_t)(row0 + 8) * DQ_ + col] =
                make_float2(oacc[dt][2] * iB, oacc[dt][3] * iB);
        }
    }
}

// =====================================================================
// launch
// =====================================================================
static inline void launch_round(const float* in, float* out, int n) {
    int n4 = n / 4;
    round_kernel<<<(n4 + 255) / 256, 256>>>((const float4*)in, (float4*)out, n4);
}
static inline void launch_split(const float* in, __nv_bfloat16* hi, __nv_bfloat16* lo, int n) {
    int n2 = n / 2;
    split_kernel<<<(n2 + 255) / 256, 256>>>((const float2*)in,
        (__nv_bfloat162*)hi, (__nv_bfloat162*)lo, n2);
}

extern "C" void kernel_launch(void* const* d_in, const int* in_sizes, int n_in,
                              void* d_out, int out_size)
{
    (void)in_sizes; (void)n_in; (void)out_size;
    const float* x_q  = (const float*)d_in[0];
    const float* x_kv = (const float*)d_in[1];
    const float* Wq   = (const float*)d_in[2];
    const float* Wk   = (const float*)d_in[3];
    const float* Wv   = (const float*)d_in[4];
    const float* Wo   = (const float*)d_in[5];
    float* out = (float*)d_out;

    float *Q, *K, *V, *AO, *xq, *xkv, *wq, *wk;
    __nv_bfloat16 *xkvh, *xkvl, *wvh, *wvl, *aoh, *aol, *woh, *wol;
    cudaGetSymbolAddress((void**)&Q,    g_Q);
    cudaGetSymbolAddress((void**)&K,    g_K);
    cudaGetSymbolAddress((void**)&V,    g_V);
    cudaGetSymbolAddress((void**)&AO,   g_AO);
    cudaGetSymbolAddress((void**)&xq,   g_xq);
    cudaGetSymbolAddress((void**)&xkv,  g_xkv);
    cudaGetSymbolAddress((void**)&wq,   g_wq);
    cudaGetSymbolAddress((void**)&wk,   g_wk);
    cudaGetSymbolAddress((void**)&xkvh, g_xkv_h);
    cudaGetSymbolAddress((void**)&xkvl, g_xkv_l);
    cudaGetSymbolAddress((void**)&wvh,  g_wv_h);
    cudaGetSymbolAddress((void**)&wvl,  g_wv_l);
    cudaGetSymbolAddress((void**)&aoh,  g_ao_h);
    cudaGetSymbolAddress((void**)&aol,  g_ao_l);
    cudaGetSymbolAddress((void**)&woh,  g_wo_h);
    cudaGetSymbolAddress((void**)&wol,  g_wo_l);

    cudaFuncSetAttribute(gemm_mma, cudaFuncAttributeMaxDynamicSharedMemorySize, GEMM_SMEM);
    cudaFuncSetAttribute(gemm_bf3, cudaFuncAttributeMaxDynamicSharedMemorySize, B3_SMEM);
    cudaFuncSetAttribute(flash_kernel, cudaFuncAttributeMaxDynamicSharedMemorySize, FLASH_SMEM);

    // prepasses
    launch_round(x_q,  xq,  BB * SQ * DQ_);
    launch_round(x_kv, xkv, BB * SKV * DKV_);
    launch_round(Wq, wq, DQ_ * DQ_);
    launch_round(Wk, wk, DQ_ * DKV_);
    launch_split(x_kv, xkvh, xkvl, BB * SKV * DKV_);
    launch_split(Wv,   wvh,  wvl,  DQ_ * DKV_);
    launch_split(Wo,   woh,  wol,  DQ_ * DQ_);

    // Q = x_q @ Wq^T  (tf32 — softmax-attenuated path)
    gemm_mma<<<dim3(DQ_ / 128, (BB * SQ) / 128),  256, GEMM_SMEM>>>(xq,  wq, Q, BB * SQ,  DQ_, DQ_);
    // K = x_kv @ Wk^T (tf32)
    gemm_mma<<<dim3(DQ_ / 128, (BB * SKV) / 128), 256, GEMM_SMEM>>>(xkv, wk, K, BB * SKV, DQ_, DKV_);
    // V = x_kv @ Wv^T (bf16x3)
    gemm_bf3<<<dim3(DQ_ / 128, (BB * SKV) / 128), 256, B3_SMEM>>>(
        xkvh, xkvl, wvh, wvl, V, BB * SKV, DQ_, DKV_);
    // attention (FA2-style, 128-query tiles)
    flash_kernel<<<dim3(SQ / 128, BB * NH), 256, FLASH_SMEM>>>();
    // split AO, then out = AO @ Wo^T (bf16x3)
    launch_split(AO, aoh, aol, BB * SQ * DQ_);
    gemm_bf3<<<dim3(DQ_ / 128, (BB * SQ) / 128), 256, B3_SMEM>>>(
        aoh, aol, woh, wol, out, BB * SQ, DQ_, DQ_);
}

// round 9
// speedup vs baseline: 3.5235x; 1.2905x over previous
#include <cuda_runtime.h>
#include <cuda_bf16.h>
#include <math.h>
#include <cstdint>

// ---------------- problem constants ----------------
#define BB   2
#define SQ   1024
#define SKV  4096
#define DQ_  1024
#define DKV_ 768
#define NH   16
#define HD   64

// ---------------- scratch ----------------
__device__ float g_V [BB * SKV * DQ_];                       // fp32 V (precision path)
__device__ __align__(256) __nv_bfloat16 g_Qb[BB * SQ  * DQ_];  // bf16 Q (pre-scaled 1/64)
__device__ __align__(256) __nv_bfloat16 g_Kb[BB * SKV * DQ_];  // bf16 K
// bf16 hi/lo splits
__device__ __align__(256) __nv_bfloat16 g_xkv_h[BB * SKV * DKV_];
__device__ __align__(256) __nv_bfloat16 g_xkv_l[BB * SKV * DKV_];
__device__ __align__(256) __nv_bfloat16 g_wv_h [DQ_ * DKV_];
__device__ __align__(256) __nv_bfloat16 g_wv_l [DQ_ * DKV_];
__device__ __align__(256) __nv_bfloat16 g_ao_h [BB * SQ * DQ_];
__device__ __align__(256) __nv_bfloat16 g_ao_l [BB * SQ * DQ_];
__device__ __align__(256) __nv_bfloat16 g_wo_h [DQ_ * DQ_];
__device__ __align__(256) __nv_bfloat16 g_wo_l [DQ_ * DQ_];
// bf16 single-precision operands (Q/K projection path)
__device__ __align__(256) __nv_bfloat16 g_xq_h[BB * SQ * DQ_];
__device__ __align__(256) __nv_bfloat16 g_wq_h[DQ_ * DQ_];
__device__ __align__(256) __nv_bfloat16 g_wk_h[DQ_ * DKV_];

// =====================================================================
// helpers
// =====================================================================
__device__ __forceinline__ uint32_t smem_u32(const void* p) {
    uint32_t a;
    asm("{ .reg .u64 t; cvta.to.shared.u64 t, %1; cvt.u32.u64 %0, t; }" : "=r"(a) : "l"(p));
    return a;
}
__device__ __forceinline__ void cp16(uint32_t dst, const void* src) {
    asm volatile("cp.async.cg.shared.global [%0], [%1], 16;" :: "r"(dst), "l"(src) : "memory");
}
__device__ __forceinline__ void cp_commit() {
    asm volatile("cp.async.commit_group;" ::: "memory");
}
__device__ __forceinline__ void cp_wait1() {
    asm volatile("cp.async.wait_group 1;" ::: "memory");
}
__device__ __forceinline__ uint32_t pack_bf16(__nv_bfloat16 a, __nv_bfloat16 b) {
    __nv_bfloat162 t{a, b};
    return *(uint32_t*)&t;
}
__device__ __forceinline__ uint32_t pack_hi(float x, float y) {
    return pack_bf16(__float2bfloat16_rn(x), __float2bfloat16_rn(y));
}
__device__ __forceinline__ uint32_t pack_lo(float x, float y) {
    __nv_bfloat16 hx = __float2bfloat16_rn(x);
    __nv_bfloat16 hy = __float2bfloat16_rn(y);
    return pack_bf16(__float2bfloat16_rn(x - __bfloat162float(hx)),
                     __float2bfloat16_rn(y - __bfloat162float(hy)));
}

// bf16 m16n8k16: D += A * B^T
__device__ __forceinline__ void mma_bf16(float* d, const uint32_t* a, const uint32_t* b) {
    asm volatile(
        "mma.sync.aligned.m16n8k16.row.col.f32.bf16.bf16.f32 "
        "{%0,%1,%2,%3}, {%4,%5,%6,%7}, {%8,%9}, {%0,%1,%2,%3};"
        : "+f"(d[0]), "+f"(d[1]), "+f"(d[2]), "+f"(d[3])
        : "r"(a[0]), "r"(a[1]), "r"(a[2]), "r"(a[3]),
          "r"(b[0]), "r"(b[1]));
}

// =====================================================================
// prepass kernels
// =====================================================================
__global__ void split_kernel(const float2* __restrict__ in,
                             __nv_bfloat162* __restrict__ hi,
                             __nv_bfloat162* __restrict__ lo, int n2) {
    int i = blockIdx.x * blockDim.x + threadIdx.x;
    if (i < n2) {
        float2 v = in[i];
        __nv_bfloat16 hx = __float2bfloat16_rn(v.x);
        __nv_bfloat16 hy = __float2bfloat16_rn(v.y);
        __nv_bfloat16 lx = __float2bfloat16_rn(v.x - __bfloat162float(hx));
        __nv_bfloat16 ly = __float2bfloat16_rn(v.y - __bfloat162float(hy));
        hi[i] = __nv_bfloat162{hx, hy};
        lo[i] = __nv_bfloat162{lx, ly};
    }
}

__global__ void cvt_kernel(const float2* __restrict__ in,
                           __nv_bfloat162* __restrict__ out, int n2, float scale) {
    int i = blockIdx.x * blockDim.x + threadIdx.x;
    if (i < n2) {
        float2 v = in[i];
        out[i] = __nv_bfloat162{__float2bfloat16_rn(v.x * scale),
                                __float2bfloat16_rn(v.y * scale)};
    }
}

// =====================================================================
// single-pass bf16 NT GEMM: Cb[M,N](bf16) = A[M,K](bf16) * B[N,K]^T(bf16)
// softmax-attenuated paths (Q/K projections). CTA 128x128, BK=32,
// 3-stage cp.async, 256 threads, warp tile 64x32. pitch 20 words.
// =====================================================================
#define BP        20
#define B1STAGE_U (2 * 128 * BP)
#define B1STAGES  3
#define B1_SMEM   (B1STAGES * B1STAGE_U * 4)

__global__ __launch_bounds__(256) void gemm_bf1(
    const __nv_bfloat16* __restrict__ A, const __nv_bfloat16* __restrict__ B,
    __nv_bfloat16* __restrict__ Cb, int M, int N, int K_)
{
    extern __shared__ uint32_t smu[];
    const uint32_t sb = smem_u32(smu);

    const int tid  = threadIdx.x;
    const int wid  = tid >> 5;
    const int lane = tid & 31;
    const int r8   = lane >> 2;
    const int c4   = lane & 3;
    const int wm   = (wid & 1) * 64;
    const int wn   = (wid >> 1) * 32;
    const int bm   = blockIdx.y * 128;
    const int bn   = blockIdx.x * 128;
    const int nk   = K_ >> 5;

    float acc[4][4][4];
    #pragma unroll
    for (int mt = 0; mt < 4; mt++)
        #pragma unroll
        for (int nt = 0; nt < 4; nt++)
            #pragma unroll
            for (int j = 0; j < 4; j++) acc[mt][nt][j] = 0.0f;

    auto issue = [&](int kc) {
        const int s = kc % B1STAGES;
        const uint32_t base = sb + (uint32_t)(s * B1STAGE_U) * 4;
        const __nv_bfloat16* gA = A + (size_t)bm * K_ + kc * 32;
        const __nv_bfloat16* gB = B + (size_t)bn * K_ + kc * 32;
        #pragma unroll
        for (int i = 0; i < 4; i++) {
            const int idx = tid + 256 * i;     // 0..1023
            const int arr = idx >> 9;          // 0..1
            const int rem = idx & 511;
            const int row = rem >> 2, cg = rem & 3;
            const __nv_bfloat16* src = (arr ? gB : gA) + (size_t)row * K_ + cg * 8;
            cp16(base + (uint32_t)(arr * 128 * BP + row * BP + cg * 4) * 4, src);
        }
        cp_commit();
    };

    issue(0);
    issue(1);

    for (int kc = 0; kc < nk; kc++) {
        cp_wait1();
        __syncthreads();

        const uint32_t* sA = smu + (kc % B1STAGES) * B1STAGE_U;
        const uint32_t* sB = sA + 128 * BP;

        #pragma unroll
        for (int ks = 0; ks < 2; ks++) {
            const int w0 = ks * 8;
            uint32_t af[4][4], bf[4][2];
            #pragma unroll
            for (int mt = 0; mt < 4; mt++) {
                const int row = wm + mt * 16 + r8;
                af[mt][0] = sA[row * BP + w0 + c4];
                af[mt][1] = sA[(row + 8) * BP + w0 + c4];
                af[mt][2] = sA[row * BP + w0 + c4 + 4];
                af[mt][3] = sA[(row + 8) * BP + w0 + c4 + 4];
            }
            #pragma unroll
            for (int nt = 0; nt < 4; nt++) {
                const int col = wn + nt * 8 + r8;
                bf[nt][0] = sB[col * BP + w0 + c4];
                bf[nt][1] = sB[col * BP + w0 + c4 + 4];
            }
            #pragma unroll
            for (int mt = 0; mt < 4; mt++)
                #pragma unroll
                for (int nt = 0; nt < 4; nt++)
                    mma_bf16(acc[mt][nt], af[mt], bf[nt]);
        }
        __syncthreads();
        if (kc + 2 < nk) issue(kc + 2);
    }

    // epilogue: bf16 packed output (adjacent col pair per u32)
    uint32_t* Cw = (uint32_t*)Cb;
    const int npitch = N >> 1;
    #pragma unroll
    for (int mt = 0; mt < 4; mt++) {
        const int row = bm + wm + mt * 16 + r8;
        #pragma unroll
        for (int nt = 0; nt < 4; nt++) {
            const int colw = (bn + wn + nt * 8) / 2 + c4;
            Cw[(size_t)row * npitch + colw] =
                pack_hi(acc[mt][nt][0], acc[mt][nt][1]);
            Cw[(size_t)(row + 8) * npitch + colw] =
                pack_hi(acc[mt][nt][2], acc[mt][nt][3]);
        }
    }
}

// =====================================================================
// bf16x3 compensated NT GEMM — validated (V proj, out proj)
// =====================================================================
#define BSTAGE_U  (4 * 128 * BP)
#define B3STAGES  3
#define B3_SMEM   (B3STAGES * BSTAGE_U * 4)

__global__ __launch_bounds__(256) void gemm_bf3(
    const __nv_bfloat16* __restrict__ Ah, const __nv_bfloat16* __restrict__ Al,
    const __nv_bfloat16* __restrict__ Bh, const __nv_bfloat16* __restrict__ Bl,
    float* __restrict__ C, int M, int N, int K_)
{
    extern __shared__ uint32_t smu[];
    const uint32_t sb = smem_u32(smu);

    const int tid  = threadIdx.x;
    const int wid  = tid >> 5;
    const int lane = tid & 31;
    const int r8   = lane >> 2;
    const int c4   = lane & 3;
    const int wm   = (wid & 1) * 64;
    const int wn   = (wid >> 1) * 32;
    const int bm   = blockIdx.y * 128;
    const int bn   = blockIdx.x * 128;
    const int nk   = K_ >> 5;

    float acc[4][4][4];
    #pragma unroll
    for (int mt = 0; mt < 4; mt++)
        #pragma unroll
        for (int nt = 0; nt < 4; nt++)
            #pragma unroll
            for (int j = 0; j < 4; j++) acc[mt][nt][j] = 0.0f;

    auto issue = [&](int kc) {
        const int s = kc % B3STAGES;
        const uint32_t base = sb + (uint32_t)(s * BSTAGE_U) * 4;
        const __nv_bfloat16* gsrc[4] = {
            Ah + (size_t)bm * K_ + kc * 32, Al + (size_t)bm * K_ + kc * 32,
            Bh + (size_t)bn * K_ + kc * 32, Bl + (size_t)bn * K_ + kc * 32 };
        #pragma unroll
        for (int i = 0; i < 8; i++) {
            const int idx = tid + 256 * i;
            const int arr = idx >> 9;
            const int rem = idx & 511;
            const int row = rem >> 2, cg = rem & 3;
            cp16(base + (uint32_t)(arr * 128 * BP + row * BP + cg * 4) * 4,
                 gsrc[arr] + (size_t)row * K_ + cg * 8);
        }
        cp_commit();
    };

    issue(0);
    issue(1);

    for (int kc = 0; kc < nk; kc++) {
        cp_wait1();
        __syncthreads();

        const uint32_t* sAh = smu + (kc % B3STAGES) * BSTAGE_U;
        const uint32_t* sAl = sAh + 128 * BP;
        const uint32_t* sBh = sAl + 128 * BP;
        const uint32_t* sBl = sBh + 128 * BP;

        #pragma unroll
        for (int ks = 0; ks < 2; ks++) {
            const int w0 = ks * 8;
            uint32_t ah[4][4], al[4][4], bh[4][2], bl[4][2];
            #pragma unroll
            for (int mt = 0; mt < 4; mt++) {
                const int row = wm + mt * 16 + r8;
                ah[mt][0] = sAh[row * BP + w0 + c4];
                ah[mt][1] = sAh[(row + 8) * BP + w0 + c4];
                ah[mt][2] = sAh[row * BP + w0 + c4 + 4];
                ah[mt][3] = sAh[(row + 8) * BP + w0 + c4 + 4];
                al[mt][0] = sAl[row * BP + w0 + c4];
                al[mt][1] = sAl[(row + 8) * BP + w0 + c4];
                al[mt][2] = sAl[row * BP + w0 + c4 + 4];
                al[mt][3] = sAl[(row + 8) * BP + w0 + c4 + 4];
            }
            #pragma unroll
            for (int nt = 0; nt < 4; nt++) {
                const int col = wn + nt * 8 + r8;
                bh[nt][0] = sBh[col * BP + w0 + c4];
                bh[nt][1] = sBh[col * BP + w0 + c4 + 4];
                bl[nt][0] = sBl[col * BP + w0 + c4];
                bl[nt][1] = sBl[col * BP + w0 + c4 + 4];
            }
            #pragma unroll
            for (int mt = 0; mt < 4; mt++)
                #pragma unroll
                for (int nt = 0; nt < 4; nt++) {
                    mma_bf16(acc[mt][nt], ah[mt], bh[nt]);
                    mma_bf16(acc[mt][nt], ah[mt], bl[nt]);
                    mma_bf16(acc[mt][nt], al[mt], bh[nt]);
                }
        }
        __syncthreads();
        if (kc + 2 < nk) issue(kc + 2);
    }

    #pragma unroll
    for (int mt = 0; mt < 4; mt++) {
        const int row = bm + wm + mt * 16 + r8;
        #pragma unroll
        for (int nt = 0; nt < 4; nt++) {
            const int col = bn + wn + nt * 8 + 2 * c4;
            *(float2*)&C[(size_t)row * N + col] =
                make_float2(acc[mt][nt][0], acc[mt][nt][1]);
            *(float2*)&C[(size_t)(row + 8) * N + col] =
                make_float2(acc[mt][nt][2], acc[mt][nt][3]);
        }
    }
}

// =====================================================================
// Flash attention v5 (FA2-style, all-bf16 tensor path on attenuated S):
//   S  : bf16 mma on pre-packed bf16 Q/K (no staging conversion)
//   softmax: in-register fp32
//   PV : bf16x3 compensated (pass-through path)
//   epilogue: writes AO hi/lo splits directly (feeds out-proj bf3)
// smem: Qp[128][36]u32, Kp[64][36]u32, Vth/Vtl[64][36]u32 = 45 KB
// =====================================================================
#define HP 36
#define FLASH_SMEM ((128 * HP + 64 * HP + 2 * 64 * HP) * 4)

__global__ __launch_bounds__(256, 2) void flash_kernel()
{
    extern __shared__ uint32_t fsm[];
    uint32_t* Qp  = fsm;                 // [128][HP] bf16 pairs (k-pairs)
    uint32_t* Kp  = Qp + 128 * HP;       // [64][HP]
    uint32_t* Vth = Kp + 64 * HP;        // [64 d][HP] (kv pairs)
    uint32_t* Vtl = Vth + 64 * HP;

    const int tid  = threadIdx.x;
    const int lane = tid & 31;
    const int wid  = tid >> 5;
    const int r8   = lane >> 2;
    const int c4   = lane & 3;
    const int wm   = wid * 16;
    const int r    = tid & 63;
    const int cg   = tid >> 6;
    const int bh   = blockIdx.y;
    const int b    = bh >> 4, h = bh & 15;
    const int q0   = blockIdx.x * 128;

    const uint32_t* Qhb = (const uint32_t*)g_Qb + (size_t)bh * SQ  * (HD / 2);
    const uint32_t* Khb = (const uint32_t*)g_Kb + (size_t)bh * SKV * (HD / 2);
    const float*    Vh  = g_V + (size_t)bh * (SKV * HD);

    __nv_bfloat16* VthH = (__nv_bfloat16*)Vth;
    __nv_bfloat16* VtlH = (__nv_bfloat16*)Vtl;

    // Q tile (128 rows x 32 u32) -> Qp (already bf16, already scaled)
    #pragma unroll
    for (int it = 0; it < 4; it++) {
        int idx = tid + it * 256;           // 0..1023 uint4s
        int row = idx >> 3, cgq = idx & 7;
        uint4 v = *(const uint4*)(Qhb + (size_t)(q0 + row) * 32 + cgq * 4);
        *(uint4*)&Qp[row * HP + cgq * 4] = v;
    }

    float m0 = -INFINITY, m1 = -INFINITY, l0 = 0.0f, l1 = 0.0f;
    float oacc[8][4];
    #pragma unroll
    for (int dt = 0; dt < 8; dt++)
        #pragma unroll
        for (int j = 0; j < 4; j++) oacc[dt][j] = 0.0f;

    for (int kc = 0; kc < SKV / 64; kc++) {
        const int n0 = kc * 64;
        // preload K (bf16 u32x4) and V (fp32) into regs
        uint4 kq[2];
        float4 vv[4];
        #pragma unroll
        for (int it = 0; it < 2; it++) {
            int idx = tid + it * 256;       // 0..511 uint4s
            int row = idx >> 3, cgk = idx & 7;
            kq[it] = *(const uint4*)(Khb + (size_t)(n0 + row) * 32 + cgk * 4);
        }
        #pragma unroll
        for (int it = 0; it < 4; it++) {
            int cc = cg + it * 4;
            vv[it] = *(const float4*)(Vh + (size_t)(n0 + r) * HD + cc * 4);
        }
        __syncthreads();   // prev chunk's mma reads done
        #pragma unroll
        for (int it = 0; it < 2; it++) {
            int idx = tid + it * 256;
            int row = idx >> 3, cgk = idx & 7;
            *(uint4*)&Kp[row * HP + cgk * 4] = kq[it];
        }
        #pragma unroll
        for (int it = 0; it < 4; it++) {
            int cc = cg + it * 4;
            float vals[4] = {vv[it].x, vv[it].y, vv[it].z, vv[it].w};
            #pragma unroll
            for (int j = 0; j < 4; j++) {
                int d = cc * 4 + j;
                float v = vals[j];
                __nv_bfloat16 hv = __float2bfloat16_rn(v);
                __nv_bfloat16 lv = __float2bfloat16_rn(v - __bfloat162float(hv));
                VthH[d * (2 * HP) + r] = hv;
                VtlH[d * (2 * HP) + r] = lv;
            }
        }
        __syncthreads();

        // ---- S = Q K^T : bf16 mma, 4 k16-steps x 8 n-tiles ----
        float sf[8][4];
        #pragma unroll
        for (int nt = 0; nt < 8; nt++)
            #pragma unroll
            for (int j = 0; j < 4; j++) sf[nt][j] = 0.0f;
        #pragma unroll
        for (int ks = 0; ks < 4; ks++) {
            const int w0 = ks * 8;
            uint32_t af[4];
            af[0] = Qp[(wm + r8) * HP + w0 + c4];
            af[1] = Qp[(wm + 8 + r8) * HP + w0 + c4];
            af[2] = Qp[(wm + r8) * HP + w0 + 4 + c4];
            af[3] = Qp[(wm + 8 + r8) * HP + w0 + 4 + c4];
            #pragma unroll
            for (int nt = 0; nt < 8; nt++) {
                uint32_t bf[2];
                bf[0] = Kp[(nt * 8 + r8) * HP + w0 + c4];
                bf[1] = Kp[(nt * 8 + r8) * HP + w0 + 4 + c4];
                mma_bf16(sf[nt], af, bf);
            }
        }

        // ---- in-register online softmax ----
        float mxA = -INFINITY, mxB = -INFINITY;
        #pragma unroll
        for (int nt = 0; nt < 8; nt++) {
            mxA = fmaxf(mxA, fmaxf(sf[nt][0], sf[nt][1]));
            mxB = fmaxf(mxB, fmaxf(sf[nt][2], sf[nt][3]));
        }
        mxA = fmaxf(mxA, __shfl_xor_sync(0xffffffffu, mxA, 1));
        mxA = fmaxf(mxA, __shfl_xor_sync(0xffffffffu, mxA, 2));
        mxB = fmaxf(mxB, __shfl_xor_sync(0xffffffffu, mxB, 1));
        mxB = fmaxf(mxB, __shfl_xor_sync(0xffffffffu, mxB, 2));
        float mnA = fmaxf(m0, mxA), mnB = fmaxf(m1, mxB);
        float cA = __expf(m0 - mnA), cB = __expf(m1 - mnB);
        float sA = 0.0f, sB = 0.0f;
        #pragma unroll
        for (int nt = 0; nt < 8; nt++) {
            sf[nt][0] = __expf(sf[nt][0] - mnA);
            sf[nt][1] = __expf(sf[nt][1] - mnA);
            sf[nt][2] = __expf(sf[nt][2] - mnB);
            sf[nt][3] = __expf(sf[nt][3] - mnB);
            sA += sf[nt][0] + sf[nt][1];
            sB += sf[nt][2] + sf[nt][3];
        }
        sA += __shfl_xor_sync(0xffffffffu, sA, 1);
        sA += __shfl_xor_sync(0xffffffffu, sA, 2);
        sB += __shfl_xor_sync(0xffffffffu, sB, 1);
        sB += __shfl_xor_sync(0xffffffffu, sB, 2);
        l0 = l0 * cA + sA;  l1 = l1 * cB + sB;
        m0 = mnA;           m1 = mnB;
        #pragma unroll
        for (int dt = 0; dt < 8; dt++) {
            oacc[dt][0] *= cA; oacc[dt][1] *= cA;
            oacc[dt][2] *= cB; oacc[dt][3] *= cB;
        }

        // ---- O += P V : P A-fragments from S C-fragments, bf16x3 ----
        #pragma unroll
        for (int kg = 0; kg < 4; kg++) {
            const float* f0 = sf[2 * kg];
            const float* f1 = sf[2 * kg + 1];
            uint32_t ah[4], al[4];
            ah[0] = pack_hi(f0[0], f0[1]);  al[0] = pack_lo(f0[0], f0[1]);
            ah[1] = pack_hi(f0[2], f0[3]);  al[1] = pack_lo(f0[2], f0[3]);
            ah[2] = pack_hi(f1[0], f1[1]);  al[2] = pack_lo(f1[0], f1[1]);
            ah[3] = pack_hi(f1[2], f1[3]);  al[3] = pack_lo(f1[2], f1[3]);
            const int w0 = kg * 8;
            #pragma unroll
            for (int dt = 0; dt < 8; dt++) {
                const int col = dt * 8 + r8;
                uint32_t bhf[2], blf[2];
                bhf[0] = Vth[col * HP + w0 + c4];
                bhf[1] = Vth[col * HP + w0 + 4 + c4];
                blf[0] = Vtl[col * HP + w0 + c4];
                blf[1] = Vtl[col * HP + w0 + 4 + c4];
                mma_bf16(oacc[dt], ah, bhf);
                mma_bf16(oacc[dt], ah, blf);
                mma_bf16(oacc[dt], al, bhf);
            }
        }
    }

    // epilogue: write AO hi/lo splits directly (feeds out-proj gemm_bf3)
    {
        float iA = 1.0f / l0, iB = 1.0f / l1;
        uint32_t* AOh = (uint32_t*)g_ao_h;
        uint32_t* AOl = (uint32_t*)g_ao_l;
        const int pitchw = DQ_ / 2;
        const size_t rbase = (size_t)(b * SQ + q0 + wm + r8) * pitchw;
        #pragma unroll
        for (int dt = 0; dt < 8; dt++) {
            const int colw = h * 32 + dt * 4 + c4;
            float x0 = oacc[dt][0] * iA, y0 = oacc[dt][1] * iA;
            float x1 = oacc[dt][2] * iB, y1 = oacc[dt][3] * iB;
            AOh[rbase + colw]              = pack_hi(x0, y0);
            AOl[rbase + colw]              = pack_lo(x0, y0);
            AOh[rbase + 8 * pitchw + colw] = pack_hi(x1, y1);
            AOl[rbase + 8 * pitchw + colw] = pack_lo(x1, y1);
        }
    }
}

// =====================================================================
// launch
// =====================================================================
static inline void launch_split(const float* in, __nv_bfloat16* hi, __nv_bfloat16* lo, int n) {
    int n2 = n / 2;
    split_kernel<<<(n2 + 255) / 256, 256>>>((const float2*)in,
        (__nv_bfloat162*)hi, (__nv_bfloat162*)lo, n2);
}
static inline void launch_cvt(const float* in, __nv_bfloat16* out, int n, float scale) {
    int n2 = n / 2;
    cvt_kernel<<<(n2 + 255) / 256, 256>>>((const float2*)in,
        (__nv_bfloat162*)out, n2, scale);
}

extern "C" void kernel_launch(void* const* d_in, const int* in_sizes, int n_in,
                              void* d_out, int out_size)
{
    (void)in_sizes; (void)n_in; (void)out_size;
    const float* x_q  = (const float*)d_in[0];
    const float* x_kv = (const float*)d_in[1];
    const float* Wq   = (const float*)d_in[2];
    const float* Wk   = (const float*)d_in[3];
    const float* Wv   = (const float*)d_in[4];
    const float* Wo   = (const float*)d_in[5];
    float* out = (float*)d_out;

    float *V;
    __nv_bfloat16 *Qb, *Kb, *xkvh, *xkvl, *wvh, *wvl, *aoh, *aol, *woh, *wol;
    __nv_bfloat16 *xqh, *wqh, *wkh;
    cudaGetSymbolAddress((void**)&V,    g_V);
    cudaGetSymbolAddress((void**)&Qb,   g_Qb);
    cudaGetSymbolAddress((void**)&Kb,   g_Kb);
    cudaGetSymbolAddress((void**)&xkvh, g_xkv_h);
    cudaGetSymbolAddress((void**)&xkvl, g_xkv_l);
    cudaGetSymbolAddress((void**)&wvh,  g_wv_h);
    cudaGetSymbolAddress((void**)&wvl,  g_wv_l);
    cudaGetSymbolAddress((void**)&aoh,  g_ao_h);
    cudaGetSymbolAddress((void**)&aol,  g_ao_l);
    cudaGetSymbolAddress((void**)&woh,  g_wo_h);
    cudaGetSymbolAddress((void**)&wol,  g_wo_l);
    cudaGetSymbolAddress((void**)&xqh,  g_xq_h);
    cudaGetSymbolAddress((void**)&wqh,  g_wq_h);
    cudaGetSymbolAddress((void**)&wkh,  g_wk_h);

    cudaFuncSetAttribute(gemm_bf1, cudaFuncAttributeMaxDynamicSharedMemorySize, B1_SMEM);
    cudaFuncSetAttribute(gemm_bf3, cudaFuncAttributeMaxDynamicSharedMemorySize, B3_SMEM);
    cudaFuncSetAttribute(flash_kernel, cudaFuncAttributeMaxDynamicSharedMemorySize, FLASH_SMEM);

    // prepasses
    launch_split(x_kv, xkvh, xkvl, BB * SKV * DKV_);   // V-proj A (hi also K-proj A)
    launch_split(Wv,   wvh,  wvl,  DQ_ * DKV_);
    launch_split(Wo,   woh,  wol,  DQ_ * DQ_);
    launch_cvt(x_q, xqh, BB * SQ * DQ_, 1.0f);
    launch_cvt(Wq,  wqh, DQ_ * DQ_, 1.0f / (float)HD);  // fold 1/64 (exact in bf16)
    launch_cvt(Wk,  wkh, DQ_ * DKV_, 1.0f);

    // Q/64 = x_q @ (Wq/64)^T  (bf16 single — softmax-attenuated path)
    gemm_bf1<<<dim3(DQ_ / 128, (BB * SQ) / 128),  256, B1_SMEM>>>(xqh,  wqh, Qb, BB * SQ,  DQ_, DQ_);
    // K = x_kv @ Wk^T (bf16 single)
    gemm_bf1<<<dim3(DQ_ / 128, (BB * SKV) / 128), 256, B1_SMEM>>>(xkvh, wkh, Kb, BB * SKV, DQ_, DKV_);
    // V = x_kv @ Wv^T (bf16x3 — precision path)
    gemm_bf3<<<dim3(DQ_ / 128, (BB * SKV) / 128), 256, B3_SMEM>>>(
        xkvh, xkvl, wvh, wvl, V, BB * SKV, DQ_, DKV_);
    // attention (S bf16, softmax fp32, PV bf16x3; writes aoh/aol)
    flash_kernel<<<dim3(SQ / 128, BB * NH), 256, FLASH_SMEM>>>();
    // out = AO @ Wo^T (bf16x3 — precision path)
    gemm_bf3<<<dim3(DQ_ / 128, (BB * SQ) / 128), 256, B3_SMEM>>>(
        aoh, aol, woh, wol, out, BB * SQ, DQ_, DQ_);
}